// round 14
// baseline (speedup 1.0000x reference)
#include <cuda_runtime.h>
#include <cuda_fp16.h>
#include <stdint.h>
#include <math.h>

#define BATCH 8
#define EMB 768
#define NHEAD 12
#define NLAYER 12
#define HD 64
#define NTOK 197
#define MROWS (BATCH*NTOK)   /* 1576 */
#define MPAD 1664            /* 13*128 */
#define E3 2304
#define MLPD 3072
#define QSCALE 0.125f
#define NCLS 1000
#define BH 96                /* BATCH*NHEAD */
#define TP 256               /* padded tokens for mma M/N */
#define MP 208               /* padded m (K dim of AV) */

enum { EPI_BIAS=0, EPI_GELU=1, EPI_RES=2, EPI_QKVH=3, EPI_CQKVH=4 };

/* ---------------- weight plane offsets (elements) ---------------- */
#define OFF_PW    0ULL
#define OFF_CPW   589824ULL
#define OFF_QKV   1179648ULL
#define OFF_PROJ  22413312ULL
#define OFF_CPROJ 29491200ULL
#define OFF_FC1   36569088ULL
#define OFF_FC2   64880640ULL
#define WTOT      93192192ULL

/* ------------------------------ scratch ------------------------------ */
__device__ __half g_w[WTOT];

__device__ __half g_pat[MPAD*EMB];
__device__ __half g_tn [2*MPAD*EMB];
__device__ __half g_ctx[2*MPAD*EMB];
__device__ __half g_h  [2*(size_t)MPAD*MLPD];

__device__ float g_x[2*MROWS*EMB];
__device__ __half g_qkv[2*(size_t)MROWS*E3];

/* attention buffers (zero-initialized; pad regions never written) */
__device__ __half g_qph[(size_t)BH*TP*128];
__device__ __half g_qpl[(size_t)BH*TP*128];
__device__ __half g_kp [(size_t)BH*TP*128];
__device__ __half g_vt [(size_t)BH*64*MP];
__device__ __half g_cvt[(size_t)BH*64*MP];
__device__ __half g_sdot[(size_t)BH*TP*TP];

__device__ float g_qs2[BH*NTOK];
__device__ float g_ks2[BH*NTOK];
__device__ float g_cqsum[BH*NTOK];
__device__ float g_cksum[BH*NTOK];
__device__ float g_qkvb[NLAYER*E3];
__device__ float g_cqkvb[NLAYER*E3];
__device__ float g_pool[BATCH*EMB];
__device__ float g_pooln[BATCH*EMB];

/* ------------------------------ helpers ------------------------------ */
__device__ __forceinline__ uint32_t s2u(const void* p){
    return (uint32_t)__cvta_generic_to_shared(p);
}
__device__ __forceinline__ void cpa16(uint32_t dst, const void* src){
    asm volatile("cp.async.cg.shared.global [%0], [%1], 16;\n" :: "r"(dst), "l"(src));
}
__device__ __forceinline__ void mma16816(float* c, uint32_t a0,uint32_t a1,uint32_t a2,uint32_t a3,
                                         uint32_t b0,uint32_t b1){
    asm volatile("mma.sync.aligned.m16n8k16.row.col.f32.f16.f16.f32 "
        "{%0,%1,%2,%3},{%4,%5,%6,%7},{%8,%9},{%0,%1,%2,%3};\n"
        : "+f"(c[0]),"+f"(c[1]),"+f"(c[2]),"+f"(c[3])
        : "r"(a0),"r"(a1),"r"(a2),"r"(a3),"r"(b0),"r"(b1));
}
__device__ __forceinline__ void split_h(float f, __half& h, __half& l){
    h = __float2half_rn(f);
    l = __float2half_rn(f - __half2float(h));
}

/* ---------------- fp16 GEMM: C[M,N] = A[M,K]*B[N,K]^T ---------------- */
#define APITCH 20
#define PLANE_U32 (128*APITCH)
#define STAGE_U32 (2*PLANE_U32)
#define GEMM_SMEM (2*STAGE_U32*4)

__global__ void __launch_bounds__(256)
gemm_h(const __half* __restrict__ A,
       const __half* __restrict__ B0, const __half* __restrict__ B1,
       const float* __restrict__ bias0, const float* __restrict__ bias1,
       const float* __restrict__ gamma,
       float* __restrict__ C, __half* __restrict__ Ch,
       int N, int K, int epi0, int epi1, int aShared)
{
    extern __shared__ uint32_t smem[];
    const int tid = threadIdx.x;
    const int lane = tid & 31, wid = tid >> 5;
    const int wm = wid >> 2, wn = wid & 3;
    const int g = lane >> 2, tig = lane & 3;
    const int half_ = blockIdx.z;
    const int lmBase = blockIdx.y * 128;
    const int aBase = (aShared ? 0 : half_*MPAD) + lmBase;
    const int bn = blockIdx.x * 128;
    const int K2 = K >> 1;
    const __half* B = half_ ? B1 : B0;
    const float* bias = half_ ? bias1 : bias0;
    const int epi = half_ ? epi1 : epi0;

    const uint32_t* gA = (const uint32_t*)A;
    const uint32_t* gB = (const uint32_t*)B;
    const uint32_t sbase_u = s2u(smem);

    float acc[4][4][4];
#pragma unroll
    for (int a=0;a<4;a++)
#pragma unroll
        for (int b=0;b<4;b++)
#pragma unroll
            for (int c=0;c<4;c++) acc[a][b][c]=0.f;

    const int KT = K >> 5;

    auto fill = [&](int buf, int kt){
        uint32_t sd = sbase_u + (uint32_t)buf*STAGE_U32*4;
        int kc0 = kt*16;
#pragma unroll
        for (int i=0;i<2;i++){
            int t = tid + i*256;
            int row = t >> 2, ch = (t & 3) * 4;
            size_t ga = (size_t)(aBase+row)*K2 + kc0 + ch;
            size_t gb = (size_t)(bn + row)*K2 + kc0 + ch;
            uint32_t so = (uint32_t)(row*APITCH + ch)*4;
            cpa16(sd + so,                 gA + ga);
            cpa16(sd + PLANE_U32*4 + so,   gB + gb);
        }
        asm volatile("cp.async.commit_group;\n");
    };

    fill(0, 0);
    for (int kt=0; kt<KT; kt++){
        int buf = kt & 1;
        if (kt+1 < KT) fill(buf^1, kt+1);
        else asm volatile("cp.async.commit_group;\n");
        asm volatile("cp.async.wait_group 1;\n" ::: "memory");
        __syncthreads();

        const uint32_t* sA = smem + buf*STAGE_U32;
        const uint32_t* sB = sA + PLANE_U32;

#pragma unroll
        for (int ks=0; ks<2; ks++){
            const int kc = ks*8 + tig;
            uint32_t bh[4][2];
#pragma unroll
            for (int nt=0;nt<4;nt++){
                int n = wn*32 + nt*8 + g;
                bh[nt][0]=sB[n*APITCH+kc]; bh[nt][1]=sB[n*APITCH+kc+4];
            }
#pragma unroll
            for (int mt=0;mt<4;mt++){
                int m = wm*64 + mt*16 + g;
                uint32_t a0=sA[m*APITCH+kc],     a1=sA[(m+8)*APITCH+kc];
                uint32_t a2=sA[m*APITCH+kc+4],   a3=sA[(m+8)*APITCH+kc+4];
#pragma unroll
                for (int nt=0;nt<4;nt++){
                    mma16816(acc[mt][nt], a0,a1,a2,a3, bh[nt][0],bh[nt][1]);
                }
            }
        }
        __syncthreads();
    }

#pragma unroll
    for (int mt=0;mt<4;mt++){
        int lm0 = lmBase + wm*64 + mt*16 + g;
#pragma unroll
        for (int hf=0; hf<2; hf++){
            int lm = lm0 + hf*8;
            if (lm >= MROWS) continue;
            size_t crow = (size_t)(half_*MROWS + lm)*N;
            size_t prow = (size_t)(half_*MPAD  + lm)*N;
#pragma unroll
            for (int nt=0;nt<4;nt++){
                int gn = bn + wn*32 + nt*8 + tig*2;
                float z0 = acc[mt][nt][hf*2+0];
                float z1 = acc[mt][nt][hf*2+1];
                if (bias){ z0 += bias[gn]; z1 += bias[gn+1]; }
                if (epi == EPI_BIAS){
                    *(float2*)(C + crow + gn) = make_float2(z0, z1);
                } else if (epi == EPI_GELU){
                    float o0 = 0.5f*z0*(1.f+erff(z0*0.70710678118f));
                    float o1 = 0.5f*z1*(1.f+erff(z1*0.70710678118f));
                    __half2 hv;
                    hv.x = __float2half_rn(o0); hv.y = __float2half_rn(o1);
                    *(__half2*)(Ch + prow + gn) = hv;
                } else if (epi == EPI_RES){
                    float2 old = *(const float2*)(C + crow + gn);
                    float o0 = old.x + gamma[gn]*z0;
                    float o1 = old.y + gamma[gn+1]*z1;
                    *(float2*)(C + crow + gn) = make_float2(o0,o1);
                } else if (epi == EPI_QKVH){
                    __half2 hv;
                    hv.x = __float2half_rn(z0); hv.y = __float2half_rn(z1);
                    *(__half2*)(Ch + crow + gn) = hv;
                } else { /* EPI_CQKVH: elu+1 then fp16 */
                    float o0 = (z0>0.f)? z0+1.f : expf(z0);
                    float o1 = (z1>0.f)? z1+1.f : expf(z1);
                    __half2 hv;
                    hv.x = __float2half_rn(o0); hv.y = __float2half_rn(o1);
                    *(__half2*)(Ch + crow + gn) = hv;
                }
            }
        }
    }
}

/* ---------------- weight -> fp16 (grid-stride) ---------------- */
__global__ void wsplit_h(const float4* __restrict__ src, __half* __restrict__ hi, size_t n4)
{
    size_t stride = (size_t)gridDim.x * 256;
    for (size_t i = (size_t)blockIdx.x*256 + threadIdx.x; i < n4; i += stride){
        float4 f = src[i];
        __half2 a, b;
        a.x = __float2half_rn(f.x); a.y = __float2half_rn(f.y);
        b.x = __float2half_rn(f.z); b.y = __float2half_rn(f.w);
        *(__half2*)(hi + 4*i)   = a;
        *(__half2*)(hi + 4*i+2) = b;
    }
}

/* ---------------- merged LayerNorm -> fp16 plane ---------------- */
__global__ void __launch_bounds__(256) ln_split(const float* __restrict__ x,
        const float* __restrict__ g, const float* __restrict__ b,
        __half* __restrict__ yh)
{
    int row = blockIdx.x;
    int drow = (row < MROWS) ? row : row + (MPAD - MROWS);
    const float* xr = x + (size_t)row*EMB;
    int tid = threadIdx.x;
    float v0=xr[tid], v1=xr[tid+256], v2=xr[tid+512];
    float s  = v0+v1+v2;
    float s2 = v0*v0+v1*v1+v2*v2;
    __shared__ float red[2][8];
    int lane=tid&31, wid=tid>>5;
#pragma unroll
    for(int o=16;o;o>>=1){ s+=__shfl_xor_sync(0xffffffffu,s,o); s2+=__shfl_xor_sync(0xffffffffu,s2,o); }
    if(!lane){ red[0][wid]=s; red[1][wid]=s2; }
    __syncthreads();
    s=0.f; s2=0.f;
#pragma unroll
    for (int i=0;i<8;i++){ s+=red[0][i]; s2+=red[1][i]; }
    float mu = s * (1.f/768.f);
    float var = s2*(1.f/768.f) - mu*mu;
    float inv = rsqrtf(var + 1e-5f);
    size_t o0 = (size_t)drow*EMB;
#pragma unroll
    for (int r=0;r<3;r++){
        int e = tid + r*256;
        float v = (r==0)?v0:((r==1)?v1:v2);
        float y = (v-mu)*inv*g[e] + b[e];
        yh[o0+e] = __float2half_rn(y);
    }
}

__global__ void __launch_bounds__(256) ln_f32(const float* __restrict__ x,
        const float* __restrict__ g, const float* __restrict__ b,
        float* __restrict__ y)
{
    int row = blockIdx.x;
    const float* xr = x + (size_t)row*EMB;
    float* yr = y + (size_t)row*EMB;
    int tid = threadIdx.x;
    float v0=xr[tid], v1=xr[tid+256], v2=xr[tid+512];
    float s  = v0+v1+v2;
    float s2 = v0*v0+v1*v1+v2*v2;
    __shared__ float red[2][8];
    int lane=tid&31, wid=tid>>5;
#pragma unroll
    for(int o=16;o;o>>=1){ s+=__shfl_xor_sync(0xffffffffu,s,o); s2+=__shfl_xor_sync(0xffffffffu,s2,o); }
    if(!lane){ red[0][wid]=s; red[1][wid]=s2; }
    __syncthreads();
    s=0.f; s2=0.f;
#pragma unroll
    for (int i=0;i<8;i++){ s+=red[0][i]; s2+=red[1][i]; }
    float mu = s * (1.f/768.f);
    float var = s2*(1.f/768.f) - mu*mu;
    float inv = rsqrtf(var + 1e-5f);
    yr[tid]     = (v0-mu)*inv*g[tid]     + b[tid];
    yr[tid+256] = (v1-mu)*inv*g[tid+256] + b[tid+256];
    yr[tid+512] = (v2-mu)*inv*g[tid+512] + b[tid+512];
}

/* ---------------- im2col -> fp16 plane ---------------- */
__global__ void im2col_split(const float* __restrict__ x, __half* __restrict__ ph)
{
    int idx = blockIdx.x*blockDim.x + threadIdx.x;
    if (idx >= MROWS*EMB) return;
    int r = idx / EMB, col = idx % EMB;
    int b = r / NTOK, t = r % NTOK;
    float v = 0.f;
    if (t > 0){
        int pp = t-1;
        int py = pp/14, px = pp%14;
        int c = col >> 8, phh = (col>>4)&15, pw = col&15;
        v = x[(((size_t)b*3 + c)*224 + py*16+phh)*224 + px*16+pw];
    }
    ph[idx] = __float2half_rn(v);
}

__global__ void fill_cls(const float* __restrict__ cls, const float* __restrict__ ccls,
                         float* __restrict__ xx)
{
    int b = blockIdx.x, tid=threadIdx.x;
#pragma unroll
    for (int r=0;r<3;r++){
        int e = tid+r*256;
        xx[(size_t)b*NTOK*EMB+e]              = cls[e];
        xx[((size_t)MROWS + b*NTOK)*EMB+e]    = ccls[e];
    }
}

__global__ void build_qkvb(const float* __restrict__ qb, const float* __restrict__ vb,
                           const float* __restrict__ cqb, const float* __restrict__ cvb,
                           float* __restrict__ outv, float* __restrict__ coutv)
{
    int idx = blockIdx.x*blockDim.x+threadIdx.x;
    if (idx >= NLAYER*E3) return;
    int l = idx / E3, j = idx % E3;
    float v=0.f, cv=0.f;
    if (j < EMB)        { v=qb[l*EMB+j];        cv=cqb[l*EMB+j]; }
    else if (j >= 2*EMB){ v=vb[l*EMB+j-2*EMB];  cv=cvb[l*EMB+j-2*EMB]; }
    outv[idx]=v; coutv[idx]=cv;
}

/* -------- attention preprocess: pack Qp(hi/lo), Kp, Vt, cVt + stats --- */
__global__ void __launch_bounds__(256) attn_pre(const __half* __restrict__ qkv,
   __half* __restrict__ qph, __half* __restrict__ qpl, __half* __restrict__ kp,
   __half* __restrict__ vt, __half* __restrict__ cvt,
   float* __restrict__ qs2, float* __restrict__ ks2,
   float* __restrict__ cqsum, float* __restrict__ cksum)
{
    int grp = threadIdx.x >> 6;
    int d   = threadIdx.x & 63;
    int idx = blockIdx.x*4 + grp;
    int t  = idx % NTOK;
    int bh = idx / NTOK;
    int h  = bh % NHEAD;
    int b  = bh / NHEAD;
    size_t mb = ((size_t)(b*NTOK+t))*E3 + h*HD + d;
    size_t cb = ((size_t)(MROWS + b*NTOK+t))*E3 + h*HD + d;
    float q  = __half2float(qkv[mb])*QSCALE;
    float k  = __half2float(qkv[mb+EMB]);
    float v  = __half2float(qkv[mb+2*EMB]);
    float cq = __half2float(qkv[cb]);
    float ck = __half2float(qkv[cb+EMB]);
    float cv = __half2float(qkv[cb+2*EMB]);
    float sq = sqrtf(fmaxf(cq,1e-24f));
    float sk = sqrtf(fmaxf(ck,1e-24f));

    size_t qrow = ((size_t)bh*TP + t)*128;
    __half hh,ll;
    split_h(q, hh, ll);  qph[qrow+d]    = hh; qpl[qrow+d]    = ll;
    split_h(sq, hh, ll); qph[qrow+64+d] = hh; qpl[qrow+64+d] = ll;
    kp[qrow+d]    = __float2half_rn(k);
    kp[qrow+64+d] = __float2half_rn(sk);
    vt [((size_t)bh*64 + d)*MP + t] = __float2half_rn(v);
    cvt[((size_t)bh*64 + d)*MP + t] = __float2half_rn(cv);

    float r0=q*q, r1=k*k, r2=cq, r3=ck;
#pragma unroll
    for(int off=16;off;off>>=1){
        r0+=__shfl_xor_sync(0xffffffffu,r0,off);
        r1+=__shfl_xor_sync(0xffffffffu,r1,off);
        r2+=__shfl_xor_sync(0xffffffffu,r2,off);
        r3+=__shfl_xor_sync(0xffffffffu,r3,off);
    }
    __shared__ float sh[4][4][2];
    int lane = threadIdx.x & 31;
    int wno = (threadIdx.x >> 5) & 1;
    if(!lane){ sh[grp][0][wno]=r0; sh[grp][1][wno]=r1; sh[grp][2][wno]=r2; sh[grp][3][wno]=r3; }
    __syncthreads();
    if (d==0){
        qs2[idx]  =sh[grp][0][0]+sh[grp][0][1];
        ks2[idx]  =sh[grp][1][0]+sh[grp][1][1];
        cqsum[idx]=sh[grp][2][0]+sh[grp][2][1];
        cksum[idx]=sh[grp][3][0]+sh[grp][3][1];
    }
}

/* -------- score MMA: sdot[bh][n][m] = Qp[n]·Kp[m], K=128, 2 products --- */
#define SPITCH 68
#define SC_SMEM (3*64*SPITCH*4)
__global__ void __launch_bounds__(256) score_mma(
    const __half* __restrict__ qph, const __half* __restrict__ qpl,
    const __half* __restrict__ kp, __half* __restrict__ sdot)
{
    extern __shared__ uint32_t sm[];
    uint32_t* sQh = sm;
    uint32_t* sQl = sm + 64*SPITCH;
    uint32_t* sK  = sm + 2*64*SPITCH;
    const int tid = threadIdx.x;
    const int lane = tid & 31, wid = tid >> 5;
    const int wm = wid >> 2, wn = wid & 3;
    const int g = lane >> 2, tig = lane & 3;
    const int bh = blockIdx.z;
    const int n0 = blockIdx.y * 64;
    const int m0 = blockIdx.x * 64;
    const uint32_t sb = s2u(sm);
    const uint32_t* gQh = (const uint32_t*)qph;
    const uint32_t* gQl = (const uint32_t*)qpl;
    const uint32_t* gK  = (const uint32_t*)kp;

#pragma unroll
    for (int i=0;i<4;i++){
        int j = tid + i*256;
        int row = j >> 4, c = (j & 15)*4;
        uint32_t so = (uint32_t)(row*SPITCH + c)*4;
        size_t qa = ((size_t)bh*TP + n0 + row)*64 + c;
        size_t ka = ((size_t)bh*TP + m0 + row)*64 + c;
        cpa16(sb + so,                  gQh + qa);
        cpa16(sb + 64*SPITCH*4 + so,    gQl + qa);
        cpa16(sb + 2*64*SPITCH*4 + so,  gK  + ka);
    }
    asm volatile("cp.async.commit_group;\n");
    asm volatile("cp.async.wait_group 0;\n" ::: "memory");
    __syncthreads();

    float acc[2][2][4];
#pragma unroll
    for (int a=0;a<2;a++)
#pragma unroll
        for (int b=0;b<2;b++)
#pragma unroll
            for (int c=0;c<4;c++) acc[a][b][c]=0.f;

#pragma unroll
    for (int s=0;s<8;s++){
        int kc = s*8 + tig;
        uint32_t b0[2], b1[2];
#pragma unroll
        for (int nt=0;nt<2;nt++){
            int rb = wn*16 + nt*8 + g;
            b0[nt]=sK[rb*SPITCH+kc]; b1[nt]=sK[rb*SPITCH+kc+4];
        }
#pragma unroll
        for (int mt=0;mt<2;mt++){
            int r = wm*32 + mt*16 + g;
            uint32_t ah0=sQh[r*SPITCH+kc],     ah1=sQh[(r+8)*SPITCH+kc];
            uint32_t ah2=sQh[r*SPITCH+kc+4],   ah3=sQh[(r+8)*SPITCH+kc+4];
            uint32_t al0=sQl[r*SPITCH+kc],     al1=sQl[(r+8)*SPITCH+kc];
            uint32_t al2=sQl[r*SPITCH+kc+4],   al3=sQl[(r+8)*SPITCH+kc+4];
#pragma unroll
            for (int nt=0;nt<2;nt++){
                mma16816(acc[mt][nt], ah0,ah1,ah2,ah3, b0[nt],b1[nt]);
                mma16816(acc[mt][nt], al0,al1,al2,al3, b0[nt],b1[nt]);
            }
        }
    }

#pragma unroll
    for (int mt=0;mt<2;mt++){
#pragma unroll
        for (int hf=0;hf<2;hf++){
            int n = n0 + wm*32 + mt*16 + g + hf*8;
#pragma unroll
            for (int nt=0;nt<2;nt++){
                int m = m0 + wn*16 + nt*8 + tig*2;
                __half2 hv;
                hv.x = __float2half_rn(acc[mt][nt][hf*2]);
                hv.y = __float2half_rn(acc[mt][nt][hf*2+1]);
                *(__half2*)&sdot[((size_t)bh*TP + n)*TP + m] = hv;
            }
        }
    }
}

/* -------- fused softmax + AV MMA: ctx[n][d] = softmax(...)·Vt ----------
   grid (4, BH, 2). Softmax for 64 rows computed into the A smem tile
   (fp16 in place), overlapped with the Vt cp.async; then single-product
   MMA over K=208.                                                        */
#define AVPITCH 108
#define AV_SMEM (2*64*AVPITCH*4)
__global__ void __launch_bounds__(256) av_soft(
    const __half* __restrict__ sdot,
    const float* __restrict__ qs2, const float* __restrict__ cqsum,
    const float* __restrict__ ks2, const float* __restrict__ cksum,
    const float* __restrict__ relb,
    const __half* __restrict__ vt, const __half* __restrict__ cvt,
    __half* __restrict__ ctx)
{
    extern __shared__ uint32_t sm[];
    uint32_t* sAh = sm;
    uint32_t* sB  = sm + 64*AVPITCH;
    __half* sAhalf = (__half*)sm;
    const int tid = threadIdx.x;
    const int lane = tid & 31, wid = tid >> 5;
    const int wm = wid >> 2, wn = wid & 3;
    const int g = lane >> 2, tig = lane & 3;
    const int n0 = blockIdx.x * 64;
    const int bh = blockIdx.y;
    const int path = blockIdx.z;
    const int hh = bh % NHEAD;
    const uint32_t sb = s2u(sm);
    const uint32_t* gB  = (const uint32_t*)(path ? cvt : vt);

    /* launch B tile load (overlaps with softmax below) */
#pragma unroll
    for (int i=0;i<7;i++){
        int j = tid + i*256;
        if (j < 1664){
            int row = j / 26, c = (j % 26)*4;
            size_t ba = ((size_t)bh*64 + row)*104 + c;
            cpa16(sb + (uint32_t)(64*AVPITCH + row*AVPITCH + c)*4, gB + ba);
        }
    }
    asm volatile("cp.async.commit_group;\n");

    /* softmax for rows n0..n0+63 into sA (fp16 halves at pitch 2*AVPITCH) */
    for (int r = wid; r < 64; r += 8){
        int n = n0 + r;
        __half* arow = sAhalf + (size_t)r*(2*AVPITCH);
        if (n >= NTOK){
            for (int m=lane; m<MP; m+=32) arow[m] = __float2half_rn(0.f);
            continue;
        }
        float rq = qs2[bh*NTOK+n] + cqsum[bh*NTOK+n];
        const __half* srow = sdot + ((size_t)bh*TP + n)*TP;
        const float* rrow = relb + ((size_t)hh*NTOK + n)*NTOK;
        float mx = -1e30f;
        for (int m=lane; m<MP; m+=32){
            if (m < NTOK){
                float w = -2.f*__half2float(srow[m]) + rq + ks2[bh*NTOK+m] + cksum[bh*NTOK+m];
                float s = 1.f/(1.f+expf(w - 1e-24f));
                float val = s + rrow[m];
                arow[m] = __float2half_rn(val);
                mx = fmaxf(mx, val);
            } else {
                arow[m] = __float2half_rn(0.f);
            }
        }
#pragma unroll
        for (int o=16;o;o>>=1) mx = fmaxf(mx, __shfl_xor_sync(0xffffffffu,mx,o));
        float sum = 0.f;
        for (int m=lane; m<NTOK; m+=32){
            float e = expf(__half2float(arow[m])-mx);
            arow[m] = __float2half_rn(e);
            sum += e;
        }
#pragma unroll
        for (int o=16;o;o>>=1) sum += __shfl_xor_sync(0xffffffffu,sum,o);
        float inv = 1.f/sum;
        for (int m=lane; m<NTOK; m+=32){
            float a = __half2float(arow[m])*inv;
            if (path) a = a*a;
            arow[m] = __float2half_rn(a);
        }
    }

    asm volatile("cp.async.wait_group 0;\n" ::: "memory");
    __syncthreads();

    float acc[2][2][4];
#pragma unroll
    for (int a=0;a<2;a++)
#pragma unroll
        for (int b=0;b<2;b++)
#pragma unroll
            for (int c=0;c<4;c++) acc[a][b][c]=0.f;

    for (int s=0;s<13;s++){
        int kc = s*8 + tig;
        uint32_t b0[2], b1[2];
#pragma unroll
        for (int nt=0;nt<2;nt++){
            int rb = wn*16 + nt*8 + g;
            b0[nt]=sB[rb*AVPITCH+kc]; b1[nt]=sB[rb*AVPITCH+kc+4];
        }
#pragma unroll
        for (int mt=0;mt<2;mt++){
            int r = wm*32 + mt*16 + g;
            uint32_t a0=sAh[r*AVPITCH+kc],     a1=sAh[(r+8)*AVPITCH+kc];
            uint32_t a2=sAh[r*AVPITCH+kc+4],   a3=sAh[(r+8)*AVPITCH+kc+4];
#pragma unroll
            for (int nt=0;nt<2;nt++){
                mma16816(acc[mt][nt], a0,a1,a2,a3, b0[nt],b1[nt]);
            }
        }
    }

    const int b = bh / NHEAD;
#pragma unroll
    for (int mt=0;mt<2;mt++){
#pragma unroll
        for (int hf=0;hf<2;hf++){
            int n = n0 + wm*32 + mt*16 + g + hf*8;
            if (n >= NTOK) continue;
            size_t row = (size_t)(path*MPAD + b*NTOK + n)*EMB + hh*64;
#pragma unroll
            for (int nt=0;nt<2;nt++){
                int d0 = wn*16 + nt*8 + tig*2;
                __half2 hv;
                hv.x = __float2half_rn(acc[mt][nt][hf*2]);
                hv.y = __float2half_rn(acc[mt][nt][hf*2+1]);
                *(__half2*)(ctx + row + d0) = hv;
            }
        }
    }
}

/* ------------------------------ tail ---------------------------------- */
__global__ void __launch_bounds__(256) pool_kernel(const float* __restrict__ xx, float* __restrict__ pool)
{
    int b = blockIdx.x;
    int tid=threadIdx.x;
#pragma unroll
    for (int r=0;r<3;r++){
        int e = tid + r*256;
        float s=0.f;
        for (int n=1;n<NTOK;n++) s += xx[((size_t)(b*NTOK+n))*EMB+e];
        pool[b*EMB+e]=s*(1.f/196.f);
    }
}

__global__ void head_kernel(const float* __restrict__ t, const float* __restrict__ w,
                            const float* __restrict__ hb, float* __restrict__ out)
{
    int idx = blockIdx.x*blockDim.x + threadIdx.x;
    if (idx >= BATCH*NCLS) return;
    int b = idx/NCLS, c = idx%NCLS;
    const float* tr = t + b*EMB;
    const float* wr = w + (size_t)c*EMB;
    float s = hb[c];
    for (int e=0;e<EMB;e+=4){
        float4 tv=*(const float4*)(tr+e);
        float4 wv=*(const float4*)(wr+e);
        s += tv.x*wv.x+tv.y*wv.y+tv.z*wv.z+tv.w*wv.w;
    }
    out[idx]=s;
}

/* ------------------------------ host ---------------------------------- */
extern "C" void kernel_launch(void* const* d_in, const int* in_sizes, int n_in,
                              void* d_out, int out_size)
{
    const float* x        = (const float*)d_in[0];
    const float* relb     = (const float*)d_in[1];
    const float* patch_w  = (const float*)d_in[2];
    const float* patch_b  = (const float*)d_in[3];
    const float* cpatch_w = (const float*)d_in[4];
    const float* cpatch_b = (const float*)d_in[5];
    const float* cls      = (const float*)d_in[6];
    const float* ccls     = (const float*)d_in[7];
    const float* n1g      = (const float*)d_in[8];
    const float* n1b      = (const float*)d_in[9];
    const float* qkvw     = (const float*)d_in[10];
    const float* qb       = (const float*)d_in[11];
    const float* vb       = (const float*)d_in[12];
    const float* cqb      = (const float*)d_in[13];
    const float* cvb      = (const float*)d_in[14];
    const float* projw    = (const float*)d_in[15];
    const float* projb    = (const float*)d_in[16];
    const float* cprojw   = (const float*)d_in[17];
    const float* cprojb   = (const float*)d_in[18];
    const float* gamma1   = (const float*)d_in[19];
    const float* gamma2   = (const float*)d_in[20];
    const float* n2g      = (const float*)d_in[21];
    const float* n2b      = (const float*)d_in[22];
    const float* fc1w     = (const float*)d_in[23];
    const float* fc1b     = (const float*)d_in[24];
    const float* fc2w     = (const float*)d_in[25];
    const float* fc2b     = (const float*)d_in[26];
    const float* fng      = (const float*)d_in[27];
    const float* fnb      = (const float*)d_in[28];
    const float* headw    = (const float*)d_in[29];
    const float* headb    = (const float*)d_in[30];
    float* out = (float*)d_out;

    static int attr_set = 0;
    if (!attr_set){
        cudaFuncSetAttribute(gemm_h, cudaFuncAttributeMaxDynamicSharedMemorySize, GEMM_SMEM);
        cudaFuncSetAttribute(score_mma, cudaFuncAttributeMaxDynamicSharedMemorySize, SC_SMEM);
        cudaFuncSetAttribute(av_soft, cudaFuncAttributeMaxDynamicSharedMemorySize, AV_SMEM);
        attr_set = 1;
    }

    __half *w,*pat,*tn,*ctx,*hbuf,*qkvh,*qph,*qpl,*kp,*vt,*cvt,*sdot;
    float *p_x,*p_qs2,*p_ks2,*p_cqsum,*p_cksum,*p_qkvb,*p_cqkvb,*p_pool,*p_pooln;
    cudaGetSymbolAddress((void**)&w, g_w);
    cudaGetSymbolAddress((void**)&pat, g_pat);
    cudaGetSymbolAddress((void**)&tn, g_tn);
    cudaGetSymbolAddress((void**)&ctx, g_ctx);
    cudaGetSymbolAddress((void**)&hbuf, g_h);
    cudaGetSymbolAddress((void**)&qkvh, g_qkv);
    cudaGetSymbolAddress((void**)&qph, g_qph);
    cudaGetSymbolAddress((void**)&qpl, g_qpl);
    cudaGetSymbolAddress((void**)&kp,  g_kp);
    cudaGetSymbolAddress((void**)&vt,  g_vt);
    cudaGetSymbolAddress((void**)&cvt, g_cvt);
    cudaGetSymbolAddress((void**)&sdot,g_sdot);
    cudaGetSymbolAddress((void**)&p_x,    g_x);
    cudaGetSymbolAddress((void**)&p_qs2,  g_qs2);
    cudaGetSymbolAddress((void**)&p_ks2,  g_ks2);
    cudaGetSymbolAddress((void**)&p_cqsum,g_cqsum);
    cudaGetSymbolAddress((void**)&p_cksum,g_cksum);
    cudaGetSymbolAddress((void**)&p_qkvb, g_qkvb);
    cudaGetSymbolAddress((void**)&p_cqkvb,g_cqkvb);
    cudaGetSymbolAddress((void**)&p_pool, g_pool);
    cudaGetSymbolAddress((void**)&p_pooln,g_pooln);

    auto wsp = [&](const float* src, size_t off, size_t cnt){
        size_t n4 = cnt/4;
        unsigned blocks = (unsigned)((n4 + 1023)/1024);
        wsplit_h<<<blocks,256>>>((const float4*)src, w+off, n4);
    };
    wsp(patch_w,  OFF_PW,    589824);
    wsp(cpatch_w, OFF_CPW,   589824);
    wsp(qkvw,     OFF_QKV,   21233664);
    wsp(projw,    OFF_PROJ,  7077888);
    wsp(cprojw,   OFF_CPROJ, 7077888);
    wsp(fc1w,     OFF_FC1,   28311552);
    wsp(fc2w,     OFF_FC2,   28311552);

    build_qkvb<<<(NLAYER*E3+255)/256,256>>>(qb,vb,cqb,cvb,p_qkvb,p_cqkvb);
    im2col_split<<<(MROWS*EMB+255)/256,256>>>(x, pat);

    gemm_h<<<dim3(EMB/128,13,2),256,GEMM_SMEM>>>(
        pat, w+OFF_PW, w+OFF_CPW,
        patch_b, cpatch_b, nullptr, p_x, nullptr, EMB, EMB, EPI_BIAS, EPI_BIAS, 1);
    fill_cls<<<BATCH,256>>>(cls, ccls, p_x);

    for (int i=0;i<NLAYER;i++){
        size_t qkv_o  = OFF_QKV   + (size_t)i*E3*EMB;
        size_t proj_o = OFF_PROJ  + (size_t)i*EMB*EMB;
        size_t cprj_o = OFF_CPROJ + (size_t)i*EMB*EMB;
        size_t fc1_o  = OFF_FC1   + (size_t)i*(size_t)MLPD*EMB;
        size_t fc2_o  = OFF_FC2   + (size_t)i*(size_t)EMB*MLPD;

        ln_split<<<2*MROWS,256>>>(p_x, n1g+i*EMB, n1b+i*EMB, tn);
        gemm_h<<<dim3(E3/128,13,2),256,GEMM_SMEM>>>(
            tn, w+qkv_o, w+qkv_o,
            p_qkvb+i*E3, p_cqkvb+i*E3, nullptr, nullptr, qkvh,
            E3, EMB, EPI_QKVH, EPI_CQKVH, 0);

        attn_pre<<<BATCH*NHEAD*NTOK/4,256>>>(qkvh, qph,qpl,kp,vt,cvt,
                                             p_qs2,p_ks2,p_cqsum,p_cksum);
        score_mma<<<dim3(4,4,BH),256,SC_SMEM>>>(qph,qpl,kp,sdot);
        av_soft<<<dim3(4,BH,2),256,AV_SMEM>>>(sdot,p_qs2,p_cqsum,p_ks2,p_cksum,relb,
                                              vt,cvt,ctx);

        gemm_h<<<dim3(EMB/128,13,2),256,GEMM_SMEM>>>(
            ctx, w+proj_o, w+cprj_o,
            projb+i*EMB, cprojb+i*EMB, gamma1+i*EMB, p_x, nullptr,
            EMB, EMB, EPI_RES, EPI_RES, 0);

        ln_split<<<2*MROWS,256>>>(p_x, n2g+i*EMB, n2b+i*EMB, tn);
        gemm_h<<<dim3(MLPD/128,13,2),256,GEMM_SMEM>>>(
            tn, w+fc1_o, w+fc1_o,
            fc1b+i*MLPD, fc1b+i*MLPD, nullptr, nullptr, hbuf,
            MLPD, EMB, EPI_GELU, EPI_GELU, 0);
        gemm_h<<<dim3(EMB/128,13,2),256,GEMM_SMEM>>>(
            hbuf, w+fc2_o, w+fc2_o,
            fc2b+i*EMB, fc2b+i*EMB, gamma2+i*EMB, p_x, nullptr,
            EMB, MLPD, EPI_RES, EPI_RES, 0);
    }

    pool_kernel<<<BATCH,256>>>(p_x, p_pool);
    ln_f32<<<BATCH,256>>>(p_pool, fng, fnb, p_pooln);
    head_kernel<<<(BATCH*NCLS+255)/256,256>>>(p_pooln, headw, headb, out);
}

// round 15
// speedup vs baseline: 1.0612x; 1.0612x over previous
#include <cuda_runtime.h>
#include <cuda_fp16.h>
#include <stdint.h>
#include <math.h>

#define BATCH 8
#define EMB 768
#define NHEAD 12
#define NLAYER 12
#define HD 64
#define NTOK 197
#define MROWS (BATCH*NTOK)   /* 1576 */
#define MPAD 1664            /* 13*128 */
#define E3 2304
#define MLPD 3072
#define QSCALE 0.125f
#define NCLS 1000
#define BH 96                /* BATCH*NHEAD */
#define TP 256               /* padded tokens for mma M/N */
#define MP 208               /* padded m (K dim of AV) */

enum { EPI_BIAS=0, EPI_GELU=1, EPI_RES=2, EPI_QKVH=3, EPI_CQKVH=4 };

/* ---------------- weight plane offsets (elements) ---------------- */
#define OFF_PW    0ULL
#define OFF_CPW   589824ULL
#define OFF_QKV   1179648ULL
#define OFF_PROJ  22413312ULL
#define OFF_CPROJ 29491200ULL
#define OFF_FC1   36569088ULL
#define OFF_FC2   64880640ULL
#define WTOT      93192192ULL

/* ------------------------------ scratch ------------------------------ */
__device__ __half g_w[WTOT];

__device__ __half g_pat[MPAD*EMB];
__device__ __half g_tn [2*MPAD*EMB];
__device__ __half g_ctx[2*MPAD*EMB];
__device__ __half g_h  [2*(size_t)MPAD*MLPD];

__device__ float g_x[2*MROWS*EMB];
__device__ __half g_qkv[2*(size_t)MROWS*E3];

/* attention buffers (zero-initialized; pad regions never written) */
__device__ __half g_qph[(size_t)BH*TP*128];
__device__ __half g_qpl[(size_t)BH*TP*128];
__device__ __half g_kp [(size_t)BH*TP*128];
__device__ __half g_vt [(size_t)BH*64*MP];
__device__ __half g_cvt[(size_t)BH*64*MP];
__device__ __half g_sdot[(size_t)BH*TP*TP];
__device__ __half g_ah [(size_t)BH*TP*MP];
__device__ __half g_a2h[(size_t)BH*TP*MP];

__device__ float g_qs2[BH*NTOK];
__device__ float g_ks2[BH*NTOK];
__device__ float g_cqsum[BH*NTOK];
__device__ float g_cksum[BH*NTOK];
__device__ float g_qkvb[NLAYER*E3];
__device__ float g_cqkvb[NLAYER*E3];
__device__ float g_pool[BATCH*EMB];
__device__ float g_pooln[BATCH*EMB];

/* ------------------------------ helpers ------------------------------ */
__device__ __forceinline__ uint32_t s2u(const void* p){
    return (uint32_t)__cvta_generic_to_shared(p);
}
__device__ __forceinline__ void cpa16(uint32_t dst, const void* src){
    asm volatile("cp.async.cg.shared.global [%0], [%1], 16;\n" :: "r"(dst), "l"(src));
}
__device__ __forceinline__ void mma16816(float* c, uint32_t a0,uint32_t a1,uint32_t a2,uint32_t a3,
                                         uint32_t b0,uint32_t b1){
    asm volatile("mma.sync.aligned.m16n8k16.row.col.f32.f16.f16.f32 "
        "{%0,%1,%2,%3},{%4,%5,%6,%7},{%8,%9},{%0,%1,%2,%3};\n"
        : "+f"(c[0]),"+f"(c[1]),"+f"(c[2]),"+f"(c[3])
        : "r"(a0),"r"(a1),"r"(a2),"r"(a3),"r"(b0),"r"(b1));
}
__device__ __forceinline__ void split_h(float f, __half& h, __half& l){
    h = __float2half_rn(f);
    l = __float2half_rn(f - __half2float(h));
}

/* ---------------- fp16 GEMM: C[M,N] = A[M,K]*B[N,K]^T, 3-stage -------- */
#define APITCH 20
#define PLANE_U32 (128*APITCH)
#define STAGE_U32 (2*PLANE_U32)
#define GEMM_SMEM (3*STAGE_U32*4)

__global__ void __launch_bounds__(256)
gemm_h(const __half* __restrict__ A,
       const __half* __restrict__ B0, const __half* __restrict__ B1,
       const float* __restrict__ bias0, const float* __restrict__ bias1,
       const float* __restrict__ gamma,
       float* __restrict__ C, __half* __restrict__ Ch,
       int N, int K, int epi0, int epi1, int aShared)
{
    extern __shared__ uint32_t smem[];
    const int tid = threadIdx.x;
    const int lane = tid & 31, wid = tid >> 5;
    const int wm = wid >> 2, wn = wid & 3;
    const int g = lane >> 2, tig = lane & 3;
    const int half_ = blockIdx.z;
    const int lmBase = blockIdx.y * 128;
    const int aBase = (aShared ? 0 : half_*MPAD) + lmBase;
    const int bn = blockIdx.x * 128;
    const int K2 = K >> 1;
    const __half* B = half_ ? B1 : B0;
    const float* bias = half_ ? bias1 : bias0;
    const int epi = half_ ? epi1 : epi0;

    const uint32_t* gA = (const uint32_t*)A;
    const uint32_t* gB = (const uint32_t*)B;
    const uint32_t sbase_u = s2u(smem);

    float acc[4][4][4];
#pragma unroll
    for (int a=0;a<4;a++)
#pragma unroll
        for (int b=0;b<4;b++)
#pragma unroll
            for (int c=0;c<4;c++) acc[a][b][c]=0.f;

    const int KT = K >> 5;

    auto fill = [&](int buf, int kt){
        uint32_t sd = sbase_u + (uint32_t)buf*STAGE_U32*4;
        int kc0 = kt*16;
#pragma unroll
        for (int i=0;i<2;i++){
            int t = tid + i*256;
            int row = t >> 2, ch = (t & 3) * 4;
            size_t ga = (size_t)(aBase+row)*K2 + kc0 + ch;
            size_t gb = (size_t)(bn + row)*K2 + kc0 + ch;
            uint32_t so = (uint32_t)(row*APITCH + ch)*4;
            cpa16(sd + so,                 gA + ga);
            cpa16(sd + PLANE_U32*4 + so,   gB + gb);
        }
        asm volatile("cp.async.commit_group;\n");
    };

    int b0 = 0;
    fill(0, 0);
    if (KT > 1) fill(1, 1);

    for (int kt=0; kt<KT; kt++){
        int buf = kt % 3;
        if (kt+2 < KT){
            fill((kt+2)%3, kt+2);
            asm volatile("cp.async.wait_group 2;\n" ::: "memory");
        } else if (kt+1 < KT){
            asm volatile("cp.async.wait_group 1;\n" ::: "memory");
        } else {
            asm volatile("cp.async.wait_group 0;\n" ::: "memory");
        }
        __syncthreads();

        const uint32_t* sA = smem + buf*STAGE_U32;
        const uint32_t* sB = sA + PLANE_U32;

#pragma unroll
        for (int ks=0; ks<2; ks++){
            const int kc = ks*8 + tig;
            uint32_t bh[4][2];
#pragma unroll
            for (int nt=0;nt<4;nt++){
                int n = wn*32 + nt*8 + g;
                bh[nt][0]=sB[n*APITCH+kc]; bh[nt][1]=sB[n*APITCH+kc+4];
            }
#pragma unroll
            for (int mt=0;mt<4;mt++){
                int m = wm*64 + mt*16 + g;
                uint32_t a0=sA[m*APITCH+kc],     a1=sA[(m+8)*APITCH+kc];
                uint32_t a2=sA[m*APITCH+kc+4],   a3=sA[(m+8)*APITCH+kc+4];
#pragma unroll
                for (int nt=0;nt<4;nt++){
                    mma16816(acc[mt][nt], a0,a1,a2,a3, bh[nt][0],bh[nt][1]);
                }
            }
        }
        __syncthreads();
    }
    (void)b0;

#pragma unroll
    for (int mt=0;mt<4;mt++){
        int lm0 = lmBase + wm*64 + mt*16 + g;
#pragma unroll
        for (int hf=0; hf<2; hf++){
            int lm = lm0 + hf*8;
            if (lm >= MROWS) continue;
            size_t crow = (size_t)(half_*MROWS + lm)*N;
            size_t prow = (size_t)(half_*MPAD  + lm)*N;
#pragma unroll
            for (int nt=0;nt<4;nt++){
                int gn = bn + wn*32 + nt*8 + tig*2;
                float z0 = acc[mt][nt][hf*2+0];
                float z1 = acc[mt][nt][hf*2+1];
                if (bias){ z0 += bias[gn]; z1 += bias[gn+1]; }
                if (epi == EPI_BIAS){
                    *(float2*)(C + crow + gn) = make_float2(z0, z1);
                } else if (epi == EPI_GELU){
                    float o0 = 0.5f*z0*(1.f+erff(z0*0.70710678118f));
                    float o1 = 0.5f*z1*(1.f+erff(z1*0.70710678118f));
                    __half2 hv;
                    hv.x = __float2half_rn(o0); hv.y = __float2half_rn(o1);
                    *(__half2*)(Ch + prow + gn) = hv;
                } else if (epi == EPI_RES){
                    float2 old = *(const float2*)(C + crow + gn);
                    float o0 = old.x + gamma[gn]*z0;
                    float o1 = old.y + gamma[gn+1]*z1;
                    *(float2*)(C + crow + gn) = make_float2(o0,o1);
                } else if (epi == EPI_QKVH){
                    __half2 hv;
                    hv.x = __float2half_rn(z0); hv.y = __float2half_rn(z1);
                    *(__half2*)(Ch + crow + gn) = hv;
                } else { /* EPI_CQKVH: elu+1 then fp16 */
                    float o0 = (z0>0.f)? z0+1.f : expf(z0);
                    float o1 = (z1>0.f)? z1+1.f : expf(z1);
                    __half2 hv;
                    hv.x = __float2half_rn(o0); hv.y = __float2half_rn(o1);
                    *(__half2*)(Ch + crow + gn) = hv;
                }
            }
        }
    }
}

/* ---------------- weight -> fp16 (grid-stride) ---------------- */
__global__ void wsplit_h(const float4* __restrict__ src, __half* __restrict__ hi, size_t n4)
{
    size_t stride = (size_t)gridDim.x * 256;
    for (size_t i = (size_t)blockIdx.x*256 + threadIdx.x; i < n4; i += stride){
        float4 f = src[i];
        __half2 a, b;
        a.x = __float2half_rn(f.x); a.y = __float2half_rn(f.y);
        b.x = __float2half_rn(f.z); b.y = __float2half_rn(f.w);
        *(__half2*)(hi + 4*i)   = a;
        *(__half2*)(hi + 4*i+2) = b;
    }
}

/* ---------------- merged LayerNorm -> fp16 plane ---------------- */
__global__ void __launch_bounds__(256) ln_split(const float* __restrict__ x,
        const float* __restrict__ g, const float* __restrict__ b,
        __half* __restrict__ yh)
{
    int row = blockIdx.x;
    int drow = (row < MROWS) ? row : row + (MPAD - MROWS);
    const float* xr = x + (size_t)row*EMB;
    int tid = threadIdx.x;
    float v0=xr[tid], v1=xr[tid+256], v2=xr[tid+512];
    float s  = v0+v1+v2;
    float s2 = v0*v0+v1*v1+v2*v2;
    __shared__ float red[2][8];
    int lane=tid&31, wid=tid>>5;
#pragma unroll
    for(int o=16;o;o>>=1){ s+=__shfl_xor_sync(0xffffffffu,s,o); s2+=__shfl_xor_sync(0xffffffffu,s2,o); }
    if(!lane){ red[0][wid]=s; red[1][wid]=s2; }
    __syncthreads();
    s=0.f; s2=0.f;
#pragma unroll
    for (int i=0;i<8;i++){ s+=red[0][i]; s2+=red[1][i]; }
    float mu = s * (1.f/768.f);
    float var = s2*(1.f/768.f) - mu*mu;
    float inv = rsqrtf(var + 1e-5f);
    size_t o0 = (size_t)drow*EMB;
#pragma unroll
    for (int r=0;r<3;r++){
        int e = tid + r*256;
        float v = (r==0)?v0:((r==1)?v1:v2);
        float y = (v-mu)*inv*g[e] + b[e];
        yh[o0+e] = __float2half_rn(y);
    }
}

__global__ void __launch_bounds__(256) ln_f32(const float* __restrict__ x,
        const float* __restrict__ g, const float* __restrict__ b,
        float* __restrict__ y)
{
    int row = blockIdx.x;
    const float* xr = x + (size_t)row*EMB;
    float* yr = y + (size_t)row*EMB;
    int tid = threadIdx.x;
    float v0=xr[tid], v1=xr[tid+256], v2=xr[tid+512];
    float s  = v0+v1+v2;
    float s2 = v0*v0+v1*v1+v2*v2;
    __shared__ float red[2][8];
    int lane=tid&31, wid=tid>>5;
#pragma unroll
    for(int o=16;o;o>>=1){ s+=__shfl_xor_sync(0xffffffffu,s,o); s2+=__shfl_xor_sync(0xffffffffu,s2,o); }
    if(!lane){ red[0][wid]=s; red[1][wid]=s2; }
    __syncthreads();
    s=0.f; s2=0.f;
#pragma unroll
    for (int i=0;i<8;i++){ s+=red[0][i]; s2+=red[1][i]; }
    float mu = s * (1.f/768.f);
    float var = s2*(1.f/768.f) - mu*mu;
    float inv = rsqrtf(var + 1e-5f);
    yr[tid]     = (v0-mu)*inv*g[tid]     + b[tid];
    yr[tid+256] = (v1-mu)*inv*g[tid+256] + b[tid+256];
    yr[tid+512] = (v2-mu)*inv*g[tid+512] + b[tid+512];
}

/* ---------------- im2col -> fp16 plane ---------------- */
__global__ void im2col_split(const float* __restrict__ x, __half* __restrict__ ph)
{
    int idx = blockIdx.x*blockDim.x + threadIdx.x;
    if (idx >= MROWS*EMB) return;
    int r = idx / EMB, col = idx % EMB;
    int b = r / NTOK, t = r % NTOK;
    float v = 0.f;
    if (t > 0){
        int pp = t-1;
        int py = pp/14, px = pp%14;
        int c = col >> 8, phh = (col>>4)&15, pw = col&15;
        v = x[(((size_t)b*3 + c)*224 + py*16+phh)*224 + px*16+pw];
    }
    ph[idx] = __float2half_rn(v);
}

__global__ void fill_cls(const float* __restrict__ cls, const float* __restrict__ ccls,
                         float* __restrict__ xx)
{
    int b = blockIdx.x, tid=threadIdx.x;
#pragma unroll
    for (int r=0;r<3;r++){
        int e = tid+r*256;
        xx[(size_t)b*NTOK*EMB+e]              = cls[e];
        xx[((size_t)MROWS + b*NTOK)*EMB+e]    = ccls[e];
    }
}

__global__ void build_qkvb(const float* __restrict__ qb, const float* __restrict__ vb,
                           const float* __restrict__ cqb, const float* __restrict__ cvb,
                           float* __restrict__ outv, float* __restrict__ coutv)
{
    int idx = blockIdx.x*blockDim.x+threadIdx.x;
    if (idx >= NLAYER*E3) return;
    int l = idx / E3, j = idx % E3;
    float v=0.f, cv=0.f;
    if (j < EMB)        { v=qb[l*EMB+j];        cv=cqb[l*EMB+j]; }
    else if (j >= 2*EMB){ v=vb[l*EMB+j-2*EMB];  cv=cvb[l*EMB+j-2*EMB]; }
    outv[idx]=v; coutv[idx]=cv;
}

/* -------- attention preprocess: pack Qp(hi/lo), Kp, Vt, cVt + stats --- */
__global__ void __launch_bounds__(256) attn_pre(const __half* __restrict__ qkv,
   __half* __restrict__ qph, __half* __restrict__ qpl, __half* __restrict__ kp,
   __half* __restrict__ vt, __half* __restrict__ cvt,
   float* __restrict__ qs2, float* __restrict__ ks2,
   float* __restrict__ cqsum, float* __restrict__ cksum)
{
    int grp = threadIdx.x >> 6;
    int d   = threadIdx.x & 63;
    int idx = blockIdx.x*4 + grp;
    int t  = idx % NTOK;
    int bh = idx / NTOK;
    int h  = bh % NHEAD;
    int b  = bh / NHEAD;
    size_t mb = ((size_t)(b*NTOK+t))*E3 + h*HD + d;
    size_t cb = ((size_t)(MROWS + b*NTOK+t))*E3 + h*HD + d;
    float q  = __half2float(qkv[mb])*QSCALE;
    float k  = __half2float(qkv[mb+EMB]);
    float v  = __half2float(qkv[mb+2*EMB]);
    float cq = __half2float(qkv[cb]);
    float ck = __half2float(qkv[cb+EMB]);
    float cv = __half2float(qkv[cb+2*EMB]);
    float sq = sqrtf(fmaxf(cq,1e-24f));
    float sk = sqrtf(fmaxf(ck,1e-24f));

    size_t qrow = ((size_t)bh*TP + t)*128;
    __half hh,ll;
    split_h(q, hh, ll);  qph[qrow+d]    = hh; qpl[qrow+d]    = ll;
    split_h(sq, hh, ll); qph[qrow+64+d] = hh; qpl[qrow+64+d] = ll;
    kp[qrow+d]    = __float2half_rn(k);
    kp[qrow+64+d] = __float2half_rn(sk);
    vt [((size_t)bh*64 + d)*MP + t] = __float2half_rn(v);
    cvt[((size_t)bh*64 + d)*MP + t] = __float2half_rn(cv);

    float r0=q*q, r1=k*k, r2=cq, r3=ck;
#pragma unroll
    for(int off=16;off;off>>=1){
        r0+=__shfl_xor_sync(0xffffffffu,r0,off);
        r1+=__shfl_xor_sync(0xffffffffu,r1,off);
        r2+=__shfl_xor_sync(0xffffffffu,r2,off);
        r3+=__shfl_xor_sync(0xffffffffu,r3,off);
    }
    __shared__ float sh[4][4][2];
    int lane = threadIdx.x & 31;
    int wno = (threadIdx.x >> 5) & 1;
    if(!lane){ sh[grp][0][wno]=r0; sh[grp][1][wno]=r1; sh[grp][2][wno]=r2; sh[grp][3][wno]=r3; }
    __syncthreads();
    if (d==0){
        qs2[idx]  =sh[grp][0][0]+sh[grp][0][1];
        ks2[idx]  =sh[grp][1][0]+sh[grp][1][1];
        cqsum[idx]=sh[grp][2][0]+sh[grp][2][1];
        cksum[idx]=sh[grp][3][0]+sh[grp][3][1];
    }
}

/* -------- score MMA: sdot[bh][n][m] = Qp[n]·Kp[m], K=128, 2 products --- */
#define SPITCH 68
#define SC_SMEM (3*64*SPITCH*4)
__global__ void __launch_bounds__(256) score_mma(
    const __half* __restrict__ qph, const __half* __restrict__ qpl,
    const __half* __restrict__ kp, __half* __restrict__ sdot)
{
    extern __shared__ uint32_t sm[];
    uint32_t* sQh = sm;
    uint32_t* sQl = sm + 64*SPITCH;
    uint32_t* sK  = sm + 2*64*SPITCH;
    const int tid = threadIdx.x;
    const int lane = tid & 31, wid = tid >> 5;
    const int wm = wid >> 2, wn = wid & 3;
    const int g = lane >> 2, tig = lane & 3;
    const int bh = blockIdx.z;
    const int n0 = blockIdx.y * 64;
    const int m0 = blockIdx.x * 64;
    const uint32_t sb = s2u(sm);
    const uint32_t* gQh = (const uint32_t*)qph;
    const uint32_t* gQl = (const uint32_t*)qpl;
    const uint32_t* gK  = (const uint32_t*)kp;

#pragma unroll
    for (int i=0;i<4;i++){
        int j = tid + i*256;
        int row = j >> 4, c = (j & 15)*4;
        uint32_t so = (uint32_t)(row*SPITCH + c)*4;
        size_t qa = ((size_t)bh*TP + n0 + row)*64 + c;
        size_t ka = ((size_t)bh*TP + m0 + row)*64 + c;
        cpa16(sb + so,                  gQh + qa);
        cpa16(sb + 64*SPITCH*4 + so,    gQl + qa);
        cpa16(sb + 2*64*SPITCH*4 + so,  gK  + ka);
    }
    asm volatile("cp.async.commit_group;\n");
    asm volatile("cp.async.wait_group 0;\n" ::: "memory");
    __syncthreads();

    float acc[2][2][4];
#pragma unroll
    for (int a=0;a<2;a++)
#pragma unroll
        for (int b=0;b<2;b++)
#pragma unroll
            for (int c=0;c<4;c++) acc[a][b][c]=0.f;

#pragma unroll
    for (int s=0;s<8;s++){
        int kc = s*8 + tig;
        uint32_t b0[2], b1[2];
#pragma unroll
        for (int nt=0;nt<2;nt++){
            int rb = wn*16 + nt*8 + g;
            b0[nt]=sK[rb*SPITCH+kc]; b1[nt]=sK[rb*SPITCH+kc+4];
        }
#pragma unroll
        for (int mt=0;mt<2;mt++){
            int r = wm*32 + mt*16 + g;
            uint32_t ah0=sQh[r*SPITCH+kc],     ah1=sQh[(r+8)*SPITCH+kc];
            uint32_t ah2=sQh[r*SPITCH+kc+4],   ah3=sQh[(r+8)*SPITCH+kc+4];
            uint32_t al0=sQl[r*SPITCH+kc],     al1=sQl[(r+8)*SPITCH+kc];
            uint32_t al2=sQl[r*SPITCH+kc+4],   al3=sQl[(r+8)*SPITCH+kc+4];
#pragma unroll
            for (int nt=0;nt<2;nt++){
                mma16816(acc[mt][nt], ah0,ah1,ah2,ah3, b0[nt],b1[nt]);
                mma16816(acc[mt][nt], al0,al1,al2,al3, b0[nt],b1[nt]);
            }
        }
    }

#pragma unroll
    for (int mt=0;mt<2;mt++){
#pragma unroll
        for (int hf=0;hf<2;hf++){
            int n = n0 + wm*32 + mt*16 + g + hf*8;
#pragma unroll
            for (int nt=0;nt<2;nt++){
                int m = m0 + wn*16 + nt*8 + tig*2;
                __half2 hv;
                hv.x = __float2half_rn(acc[mt][nt][hf*2]);
                hv.y = __float2half_rn(acc[mt][nt][hf*2+1]);
                *(__half2*)&sdot[((size_t)bh*TP + n)*TP + m] = hv;
            }
        }
    }
}

/* -------- softmax: w -> sigmoid -> +relb -> softmax -> attn planes ----- */
__global__ void __launch_bounds__(256) attn_softmax(
    const __half* __restrict__ sdot,
    const float* __restrict__ qs2, const float* __restrict__ cqsum,
    const float* __restrict__ ks2, const float* __restrict__ cksum,
    const float* __restrict__ relb,
    __half* __restrict__ ah, __half* __restrict__ a2h)
{
    __shared__ float ssc[16][MP];
    int bh = blockIdx.y;
    int hh = bh % NHEAD;
    int n0 = blockIdx.x * 16;
    int tid = threadIdx.x;
    int wid = tid>>5, lane = tid&31;

    for (int r = wid; r < 16; r += 8){
        int n = n0 + r;
        if (n >= NTOK) continue;
        float rq = qs2[bh*NTOK+n] + cqsum[bh*NTOK+n];
        const __half* srow = sdot + ((size_t)bh*TP + n)*TP;
        float mx = -1e30f;
        for (int m=lane; m<NTOK; m+=32){
            float w = -2.f*__half2float(srow[m]) + rq + ks2[bh*NTOK+m] + cksum[bh*NTOK+m];
            float s = 1.f/(1.f+expf(w - 1e-24f));
            float val = s + relb[((size_t)hh*NTOK + n)*NTOK + m];
            ssc[r][m] = val;
            mx = fmaxf(mx, val);
        }
#pragma unroll
        for (int o=16;o;o>>=1) mx = fmaxf(mx, __shfl_xor_sync(0xffffffffu,mx,o));
        float sum = 0.f;
        for (int m=lane; m<NTOK; m+=32){
            float e = expf(ssc[r][m]-mx); ssc[r][m]=e; sum+=e;
        }
#pragma unroll
        for (int o=16;o;o>>=1) sum += __shfl_xor_sync(0xffffffffu,sum,o);
        float inv = 1.f/sum;
        size_t ob = ((size_t)bh*TP + n)*MP;
        for (int m=lane; m<NTOK; m+=32){
            float a = ssc[r][m]*inv;
            ah[ob+m]  = __float2half_rn(a);
            a2h[ob+m] = __float2half_rn(a*a);
        }
    }
}

/* -------- AV MMA: ctx[n][d] = attn·Vt, K=208, single product ----------- */
#define AVPITCH 108
#define AV_SMEM (2*64*AVPITCH*4)
__global__ void __launch_bounds__(256) av_mma(
    const __half* __restrict__ ah, const __half* __restrict__ a2h,
    const __half* __restrict__ vt, const __half* __restrict__ cvt,
    __half* __restrict__ ctx)
{
    extern __shared__ uint32_t sm[];
    uint32_t* sAh = sm;
    uint32_t* sB  = sm + 64*AVPITCH;
    const int tid = threadIdx.x;
    const int lane = tid & 31, wid = tid >> 5;
    const int wm = wid >> 2, wn = wid & 3;
    const int g = lane >> 2, tig = lane & 3;
    const int n0 = blockIdx.x * 64;
    const int bh = blockIdx.y;
    const int path = blockIdx.z;
    const uint32_t sb = s2u(sm);
    const uint32_t* gAh = (const uint32_t*)(path ? a2h : ah);
    const uint32_t* gB  = (const uint32_t*)(path ? cvt : vt);

#pragma unroll
    for (int i=0;i<7;i++){
        int j = tid + i*256;
        if (j < 1664){
            int row = j / 26, c = (j % 26)*4;
            uint32_t so = (uint32_t)(row*AVPITCH + c)*4;
            size_t aa = ((size_t)bh*TP + n0 + row)*104 + c;
            size_t ba = ((size_t)bh*64 + row)*104 + c;
            cpa16(sb + so,                 gAh + aa);
            cpa16(sb + 64*AVPITCH*4 + so,  gB  + ba);
        }
    }
    asm volatile("cp.async.commit_group;\n");
    asm volatile("cp.async.wait_group 0;\n" ::: "memory");
    __syncthreads();

    float acc[2][2][4];
#pragma unroll
    for (int a=0;a<2;a++)
#pragma unroll
        for (int b=0;b<2;b++)
#pragma unroll
            for (int c=0;c<4;c++) acc[a][b][c]=0.f;

    for (int s=0;s<13;s++){
        int kc = s*8 + tig;
        uint32_t b0[2], b1[2];
#pragma unroll
        for (int nt=0;nt<2;nt++){
            int rb = wn*16 + nt*8 + g;
            b0[nt]=sB[rb*AVPITCH+kc]; b1[nt]=sB[rb*AVPITCH+kc+4];
        }
#pragma unroll
        for (int mt=0;mt<2;mt++){
            int r = wm*32 + mt*16 + g;
            uint32_t a0=sAh[r*AVPITCH+kc],     a1=sAh[(r+8)*AVPITCH+kc];
            uint32_t a2=sAh[r*AVPITCH+kc+4],   a3=sAh[(r+8)*AVPITCH+kc+4];
#pragma unroll
            for (int nt=0;nt<2;nt++){
                mma16816(acc[mt][nt], a0,a1,a2,a3, b0[nt],b1[nt]);
            }
        }
    }

    const int b = bh / NHEAD;
    const int hh = bh % NHEAD;
#pragma unroll
    for (int mt=0;mt<2;mt++){
#pragma unroll
        for (int hf=0;hf<2;hf++){
            int n = n0 + wm*32 + mt*16 + g + hf*8;
            if (n >= NTOK) continue;
            size_t row = (size_t)(path*MPAD + b*NTOK + n)*EMB + hh*64;
#pragma unroll
            for (int nt=0;nt<2;nt++){
                int d0 = wn*16 + nt*8 + tig*2;
                __half2 hv;
                hv.x = __float2half_rn(acc[mt][nt][hf*2]);
                hv.y = __float2half_rn(acc[mt][nt][hf*2+1]);
                *(__half2*)(ctx + row + d0) = hv;
            }
        }
    }
}

/* ------------------------------ tail ---------------------------------- */
__global__ void __launch_bounds__(256) pool_kernel(const float* __restrict__ xx, float* __restrict__ pool)
{
    int b = blockIdx.x;
    int tid=threadIdx.x;
#pragma unroll
    for (int r=0;r<3;r++){
        int e = tid + r*256;
        float s=0.f;
        for (int n=1;n<NTOK;n++) s += xx[((size_t)(b*NTOK+n))*EMB+e];
        pool[b*EMB+e]=s*(1.f/196.f);
    }
}

__global__ void head_kernel(const float* __restrict__ t, const float* __restrict__ w,
                            const float* __restrict__ hb, float* __restrict__ out)
{
    int idx = blockIdx.x*blockDim.x + threadIdx.x;
    if (idx >= BATCH*NCLS) return;
    int b = idx/NCLS, c = idx%NCLS;
    const float* tr = t + b*EMB;
    const float* wr = w + (size_t)c*EMB;
    float s = hb[c];
    for (int e=0;e<EMB;e+=4){
        float4 tv=*(const float4*)(tr+e);
        float4 wv=*(const float4*)(wr+e);
        s += tv.x*wv.x+tv.y*wv.y+tv.z*wv.z+tv.w*wv.w;
    }
    out[idx]=s;
}

/* ------------------------------ host ---------------------------------- */
extern "C" void kernel_launch(void* const* d_in, const int* in_sizes, int n_in,
                              void* d_out, int out_size)
{
    const float* x        = (const float*)d_in[0];
    const float* relb     = (const float*)d_in[1];
    const float* patch_w  = (const float*)d_in[2];
    const float* patch_b  = (const float*)d_in[3];
    const float* cpatch_w = (const float*)d_in[4];
    const float* cpatch_b = (const float*)d_in[5];
    const float* cls      = (const float*)d_in[6];
    const float* ccls     = (const float*)d_in[7];
    const float* n1g      = (const float*)d_in[8];
    const float* n1b      = (const float*)d_in[9];
    const float* qkvw     = (const float*)d_in[10];
    const float* qb       = (const float*)d_in[11];
    const float* vb       = (const float*)d_in[12];
    const float* cqb      = (const float*)d_in[13];
    const float* cvb      = (const float*)d_in[14];
    const float* projw    = (const float*)d_in[15];
    const float* projb    = (const float*)d_in[16];
    const float* cprojw   = (const float*)d_in[17];
    const float* cprojb   = (const float*)d_in[18];
    const float* gamma1   = (const float*)d_in[19];
    const float* gamma2   = (const float*)d_in[20];
    const float* n2g      = (const float*)d_in[21];
    const float* n2b      = (const float*)d_in[22];
    const float* fc1w     = (const float*)d_in[23];
    const float* fc1b     = (const float*)d_in[24];
    const float* fc2w     = (const float*)d_in[25];
    const float* fc2b     = (const float*)d_in[26];
    const float* fng      = (const float*)d_in[27];
    const float* fnb      = (const float*)d_in[28];
    const float* headw    = (const float*)d_in[29];
    const float* headb    = (const float*)d_in[30];
    float* out = (float*)d_out;

    static int attr_set = 0;
    if (!attr_set){
        cudaFuncSetAttribute(gemm_h, cudaFuncAttributeMaxDynamicSharedMemorySize, GEMM_SMEM);
        cudaFuncSetAttribute(score_mma, cudaFuncAttributeMaxDynamicSharedMemorySize, SC_SMEM);
        cudaFuncSetAttribute(av_mma, cudaFuncAttributeMaxDynamicSharedMemorySize, AV_SMEM);
        attr_set = 1;
    }

    __half *w,*pat,*tn,*ctx,*hbuf,*qkvh,*qph,*qpl,*kp,*vt,*cvt,*sdot,*ahp,*a2hp;
    float *p_x,*p_qs2,*p_ks2,*p_cqsum,*p_cksum,*p_qkvb,*p_cqkvb,*p_pool,*p_pooln;
    cudaGetSymbolAddress((void**)&w, g_w);
    cudaGetSymbolAddress((void**)&pat, g_pat);
    cudaGetSymbolAddress((void**)&tn, g_tn);
    cudaGetSymbolAddress((void**)&ctx, g_ctx);
    cudaGetSymbolAddress((void**)&hbuf, g_h);
    cudaGetSymbolAddress((void**)&qkvh, g_qkv);
    cudaGetSymbolAddress((void**)&qph, g_qph);
    cudaGetSymbolAddress((void**)&qpl, g_qpl);
    cudaGetSymbolAddress((void**)&kp,  g_kp);
    cudaGetSymbolAddress((void**)&vt,  g_vt);
    cudaGetSymbolAddress((void**)&cvt, g_cvt);
    cudaGetSymbolAddress((void**)&sdot,g_sdot);
    cudaGetSymbolAddress((void**)&ahp, g_ah);
    cudaGetSymbolAddress((void**)&a2hp,g_a2h);
    cudaGetSymbolAddress((void**)&p_x,    g_x);
    cudaGetSymbolAddress((void**)&p_qs2,  g_qs2);
    cudaGetSymbolAddress((void**)&p_ks2,  g_ks2);
    cudaGetSymbolAddress((void**)&p_cqsum,g_cqsum);
    cudaGetSymbolAddress((void**)&p_cksum,g_cksum);
    cudaGetSymbolAddress((void**)&p_qkvb, g_qkvb);
    cudaGetSymbolAddress((void**)&p_cqkvb,g_cqkvb);
    cudaGetSymbolAddress((void**)&p_pool, g_pool);
    cudaGetSymbolAddress((void**)&p_pooln,g_pooln);

    auto wsp = [&](const float* src, size_t off, size_t cnt){
        size_t n4 = cnt/4;
        unsigned blocks = (unsigned)((n4 + 1023)/1024);
        wsplit_h<<<blocks,256>>>((const float4*)src, w+off, n4);
    };
    wsp(patch_w,  OFF_PW,    589824);
    wsp(cpatch_w, OFF_CPW,   589824);
    wsp(qkvw,     OFF_QKV,   21233664);
    wsp(projw,    OFF_PROJ,  7077888);
    wsp(cprojw,   OFF_CPROJ, 7077888);
    wsp(fc1w,     OFF_FC1,   28311552);
    wsp(fc2w,     OFF_FC2,   28311552);

    build_qkvb<<<(NLAYER*E3+255)/256,256>>>(qb,vb,cqb,cvb,p_qkvb,p_cqkvb);
    im2col_split<<<(MROWS*EMB+255)/256,256>>>(x, pat);

    gemm_h<<<dim3(EMB/128,13,2),256,GEMM_SMEM>>>(
        pat, w+OFF_PW, w+OFF_CPW,
        patch_b, cpatch_b, nullptr, p_x, nullptr, EMB, EMB, EPI_BIAS, EPI_BIAS, 1);
    fill_cls<<<BATCH,256>>>(cls, ccls, p_x);

    for (int i=0;i<NLAYER;i++){
        size_t qkv_o  = OFF_QKV   + (size_t)i*E3*EMB;
        size_t proj_o = OFF_PROJ  + (size_t)i*EMB*EMB;
        size_t cprj_o = OFF_CPROJ + (size_t)i*EMB*EMB;
        size_t fc1_o  = OFF_FC1   + (size_t)i*(size_t)MLPD*EMB;
        size_t fc2_o  = OFF_FC2   + (size_t)i*(size_t)EMB*MLPD;

        ln_split<<<2*MROWS,256>>>(p_x, n1g+i*EMB, n1b+i*EMB, tn);
        gemm_h<<<dim3(E3/128,13,2),256,GEMM_SMEM>>>(
            tn, w+qkv_o, w+qkv_o,
            p_qkvb+i*E3, p_cqkvb+i*E3, nullptr, nullptr, qkvh,
            E3, EMB, EPI_QKVH, EPI_CQKVH, 0);

        attn_pre<<<BATCH*NHEAD*NTOK/4,256>>>(qkvh, qph,qpl,kp,vt,cvt,
                                             p_qs2,p_ks2,p_cqsum,p_cksum);
        score_mma<<<dim3(4,4,BH),256,SC_SMEM>>>(qph,qpl,kp,sdot);
        attn_softmax<<<dim3(13,BH),256>>>(sdot,p_qs2,p_cqsum,p_ks2,p_cksum,relb,
                                          ahp,a2hp);
        av_mma<<<dim3(4,BH,2),256,AV_SMEM>>>(ahp,a2hp,vt,cvt,ctx);

        gemm_h<<<dim3(EMB/128,13,2),256,GEMM_SMEM>>>(
            ctx, w+proj_o, w+cprj_o,
            projb+i*EMB, cprojb+i*EMB, gamma1+i*EMB, p_x, nullptr,
            EMB, EMB, EPI_RES, EPI_RES, 0);

        ln_split<<<2*MROWS,256>>>(p_x, n2g+i*EMB, n2b+i*EMB, tn);
        gemm_h<<<dim3(MLPD/128,13,2),256,GEMM_SMEM>>>(
            tn, w+fc1_o, w+fc1_o,
            fc1b+i*MLPD, fc1b+i*MLPD, nullptr, nullptr, hbuf,
            MLPD, EMB, EPI_GELU, EPI_GELU, 0);
        gemm_h<<<dim3(EMB/128,13,2),256,GEMM_SMEM>>>(
            hbuf, w+fc2_o, w+fc2_o,
            fc2b+i*EMB, fc2b+i*EMB, gamma2+i*EMB, p_x, nullptr,
            EMB, MLPD, EPI_RES, EPI_RES, 0);
    }

    pool_kernel<<<BATCH,256>>>(p_x, p_pool);
    ln_f32<<<BATCH,256>>>(p_pool, fng, fnb, p_pooln);
    head_kernel<<<(BATCH*NCLS+255)/256,256>>>(p_pooln, headw, headb, out);
}

// round 16
// speedup vs baseline: 1.0740x; 1.0121x over previous
#include <cuda_runtime.h>
#include <cuda_fp16.h>
#include <stdint.h>
#include <math.h>

#define BATCH 8
#define EMB 768
#define NHEAD 12
#define NLAYER 12
#define HD 64
#define NTOK 197
#define MROWS (BATCH*NTOK)   /* 1576 */
#define MPAD 1664            /* 13*128 */
#define E3 2304
#define MLPD 3072
#define QSCALE 0.125f
#define NCLS 1000
#define BH 96                /* BATCH*NHEAD */
#define TP 256               /* padded tokens for mma M/N */
#define MP 208               /* padded m (K dim of AV) */

enum { EPI_BIAS=0, EPI_GELU=1, EPI_RES=2, EPI_QKVH=3, EPI_CQKVH=4 };

/* ---------------- weight plane offsets (elements) ---------------- */
#define OFF_PW    0ULL
#define OFF_CPW   589824ULL
#define OFF_QKV   1179648ULL
#define OFF_PROJ  22413312ULL
#define OFF_CPROJ 29491200ULL
#define OFF_FC1   36569088ULL
#define OFF_FC2   64880640ULL
#define WTOT      93192192ULL

/* ------------------------------ scratch ------------------------------ */
__device__ __half g_w[WTOT];

__device__ __half g_pat[MPAD*EMB];
__device__ __half g_tn [2*MPAD*EMB];
__device__ __half g_ctx[2*MPAD*EMB];
__device__ __half g_h  [2*(size_t)MPAD*MLPD];

__device__ float g_x[2*MROWS*EMB];
__device__ __half g_qkv[2*(size_t)MROWS*E3];

/* attention buffers (zero-initialized; pad regions never written) */
__device__ __half g_qph[(size_t)BH*TP*128];
__device__ __half g_kp [(size_t)BH*TP*128];
__device__ __half g_vt [(size_t)BH*64*MP];
__device__ __half g_cvt[(size_t)BH*64*MP];
__device__ __half g_sdot[(size_t)BH*TP*TP];
__device__ __half g_ah [(size_t)BH*TP*MP];
__device__ __half g_a2h[(size_t)BH*TP*MP];

__device__ float g_qs2[BH*NTOK];
__device__ float g_ks2[BH*NTOK];
__device__ float g_cqsum[BH*NTOK];
__device__ float g_cksum[BH*NTOK];
__device__ float g_qkvb[NLAYER*E3];
__device__ float g_cqkvb[NLAYER*E3];
__device__ float g_pool[BATCH*EMB];
__device__ float g_pooln[BATCH*EMB];

/* ------------------------------ helpers ------------------------------ */
__device__ __forceinline__ uint32_t s2u(const void* p){
    return (uint32_t)__cvta_generic_to_shared(p);
}
__device__ __forceinline__ void cpa16(uint32_t dst, const void* src){
    asm volatile("cp.async.cg.shared.global [%0], [%1], 16;\n" :: "r"(dst), "l"(src));
}
__device__ __forceinline__ void mma16816(float* c, uint32_t a0,uint32_t a1,uint32_t a2,uint32_t a3,
                                         uint32_t b0,uint32_t b1){
    asm volatile("mma.sync.aligned.m16n8k16.row.col.f32.f16.f16.f32 "
        "{%0,%1,%2,%3},{%4,%5,%6,%7},{%8,%9},{%0,%1,%2,%3};\n"
        : "+f"(c[0]),"+f"(c[1]),"+f"(c[2]),"+f"(c[3])
        : "r"(a0),"r"(a1),"r"(a2),"r"(a3),"r"(b0),"r"(b1));
}

/* ---------------- fp16 GEMM: C[M,N] = A[M,K]*B[N,K]^T, 3-stage -------- */
#define APITCH 20
#define PLANE_U32 (128*APITCH)
#define STAGE_U32 (2*PLANE_U32)
#define GEMM_SMEM (3*STAGE_U32*4)

__global__ void __launch_bounds__(256)
gemm_h(const __half* __restrict__ A,
       const __half* __restrict__ B0, const __half* __restrict__ B1,
       const float* __restrict__ bias0, const float* __restrict__ bias1,
       const float* __restrict__ gamma,
       float* __restrict__ C, __half* __restrict__ Ch,
       int N, int K, int epi0, int epi1, int aShared)
{
    extern __shared__ uint32_t smem[];
    const int tid = threadIdx.x;
    const int lane = tid & 31, wid = tid >> 5;
    const int wm = wid >> 2, wn = wid & 3;
    const int g = lane >> 2, tig = lane & 3;
    const int half_ = blockIdx.z;
    const int lmBase = blockIdx.y * 128;
    const int aBase = (aShared ? 0 : half_*MPAD) + lmBase;
    const int bn = blockIdx.x * 128;
    const int K2 = K >> 1;
    const __half* B = half_ ? B1 : B0;
    const float* bias = half_ ? bias1 : bias0;
    const int epi = half_ ? epi1 : epi0;

    const uint32_t* gA = (const uint32_t*)A;
    const uint32_t* gB = (const uint32_t*)B;
    const uint32_t sbase_u = s2u(smem);

    float acc[4][4][4];
#pragma unroll
    for (int a=0;a<4;a++)
#pragma unroll
        for (int b=0;b<4;b++)
#pragma unroll
            for (int c=0;c<4;c++) acc[a][b][c]=0.f;

    const int KT = K >> 5;

    auto fill = [&](int buf, int kt){
        uint32_t sd = sbase_u + (uint32_t)buf*STAGE_U32*4;
        int kc0 = kt*16;
#pragma unroll
        for (int i=0;i<2;i++){
            int t = tid + i*256;
            int row = t >> 2, ch = (t & 3) * 4;
            size_t ga = (size_t)(aBase+row)*K2 + kc0 + ch;
            size_t gb = (size_t)(bn + row)*K2 + kc0 + ch;
            uint32_t so = (uint32_t)(row*APITCH + ch)*4;
            cpa16(sd + so,                 gA + ga);
            cpa16(sd + PLANE_U32*4 + so,   gB + gb);
        }
        asm volatile("cp.async.commit_group;\n");
    };

    fill(0, 0);
    if (KT > 1) fill(1, 1);

    for (int kt=0; kt<KT; kt++){
        int buf = kt % 3;
        if (kt+2 < KT){
            fill((kt+2)%3, kt+2);
            asm volatile("cp.async.wait_group 2;\n" ::: "memory");
        } else if (kt+1 < KT){
            asm volatile("cp.async.wait_group 1;\n" ::: "memory");
        } else {
            asm volatile("cp.async.wait_group 0;\n" ::: "memory");
        }
        __syncthreads();

        const uint32_t* sA = smem + buf*STAGE_U32;
        const uint32_t* sB = sA + PLANE_U32;

#pragma unroll
        for (int ks=0; ks<2; ks++){
            const int kc = ks*8 + tig;
            uint32_t bh[4][2];
#pragma unroll
            for (int nt=0;nt<4;nt++){
                int n = wn*32 + nt*8 + g;
                bh[nt][0]=sB[n*APITCH+kc]; bh[nt][1]=sB[n*APITCH+kc+4];
            }
#pragma unroll
            for (int mt=0;mt<4;mt++){
                int m = wm*64 + mt*16 + g;
                uint32_t a0=sA[m*APITCH+kc],     a1=sA[(m+8)*APITCH+kc];
                uint32_t a2=sA[m*APITCH+kc+4],   a3=sA[(m+8)*APITCH+kc+4];
#pragma unroll
                for (int nt=0;nt<4;nt++){
                    mma16816(acc[mt][nt], a0,a1,a2,a3, bh[nt][0],bh[nt][1]);
                }
            }
        }
        __syncthreads();
    }

#pragma unroll
    for (int mt=0;mt<4;mt++){
        int lm0 = lmBase + wm*64 + mt*16 + g;
#pragma unroll
        for (int hf=0; hf<2; hf++){
            int lm = lm0 + hf*8;
            if (lm >= MROWS) continue;
            size_t crow = (size_t)(half_*MROWS + lm)*N;
            size_t prow = (size_t)(half_*MPAD  + lm)*N;
#pragma unroll
            for (int nt=0;nt<4;nt++){
                int gn = bn + wn*32 + nt*8 + tig*2;
                float z0 = acc[mt][nt][hf*2+0];
                float z1 = acc[mt][nt][hf*2+1];
                if (bias){ z0 += bias[gn]; z1 += bias[gn+1]; }
                if (epi == EPI_BIAS){
                    *(float2*)(C + crow + gn) = make_float2(z0, z1);
                } else if (epi == EPI_GELU){
                    float o0 = 0.5f*z0*(1.f+erff(z0*0.70710678118f));
                    float o1 = 0.5f*z1*(1.f+erff(z1*0.70710678118f));
                    __half2 hv;
                    hv.x = __float2half_rn(o0); hv.y = __float2half_rn(o1);
                    *(__half2*)(Ch + prow + gn) = hv;
                } else if (epi == EPI_RES){
                    float2 old = *(const float2*)(C + crow + gn);
                    float o0 = old.x + gamma[gn]*z0;
                    float o1 = old.y + gamma[gn+1]*z1;
                    *(float2*)(C + crow + gn) = make_float2(o0,o1);
                } else if (epi == EPI_QKVH){
                    __half2 hv;
                    hv.x = __float2half_rn(z0); hv.y = __float2half_rn(z1);
                    *(__half2*)(Ch + crow + gn) = hv;
                } else { /* EPI_CQKVH: elu+1 then fp16 */
                    float o0 = (z0>0.f)? z0+1.f : expf(z0);
                    float o1 = (z1>0.f)? z1+1.f : expf(z1);
                    __half2 hv;
                    hv.x = __float2half_rn(o0); hv.y = __float2half_rn(o1);
                    *(__half2*)(Ch + crow + gn) = hv;
                }
            }
        }
    }
}

/* ---------------- weight -> fp16 (grid-stride, 32B in / 16B out) ------ */
__global__ void wsplit_h(const float4* __restrict__ src, __half* __restrict__ hi, size_t n4)
{
    size_t n8 = n4 >> 1;
    size_t stride = (size_t)gridDim.x * 256;
    for (size_t i = (size_t)blockIdx.x*256 + threadIdx.x; i < n8; i += stride){
        float4 f0 = src[2*i], f1 = src[2*i+1];
        __half2 h0, h1, h2, h3;
        h0.x = __float2half_rn(f0.x); h0.y = __float2half_rn(f0.y);
        h1.x = __float2half_rn(f0.z); h1.y = __float2half_rn(f0.w);
        h2.x = __float2half_rn(f1.x); h2.y = __float2half_rn(f1.y);
        h3.x = __float2half_rn(f1.z); h3.y = __float2half_rn(f1.w);
        uint4 u;
        u.x = *(uint32_t*)&h0; u.y = *(uint32_t*)&h1;
        u.z = *(uint32_t*)&h2; u.w = *(uint32_t*)&h3;
        *(uint4*)(hi + 8*i) = u;
    }
}

/* ---------------- merged LayerNorm -> fp16 plane ---------------- */
__global__ void __launch_bounds__(256) ln_split(const float* __restrict__ x,
        const float* __restrict__ g, const float* __restrict__ b,
        __half* __restrict__ yh)
{
    int row = blockIdx.x;
    int drow = (row < MROWS) ? row : row + (MPAD - MROWS);
    const float* xr = x + (size_t)row*EMB;
    int tid = threadIdx.x;
    float v0=xr[tid], v1=xr[tid+256], v2=xr[tid+512];
    float s  = v0+v1+v2;
    float s2 = v0*v0+v1*v1+v2*v2;
    __shared__ float red[2][8];
    int lane=tid&31, wid=tid>>5;
#pragma unroll
    for(int o=16;o;o>>=1){ s+=__shfl_xor_sync(0xffffffffu,s,o); s2+=__shfl_xor_sync(0xffffffffu,s2,o); }
    if(!lane){ red[0][wid]=s; red[1][wid]=s2; }
    __syncthreads();
    s=0.f; s2=0.f;
#pragma unroll
    for (int i=0;i<8;i++){ s+=red[0][i]; s2+=red[1][i]; }
    float mu = s * (1.f/768.f);
    float var = s2*(1.f/768.f) - mu*mu;
    float inv = rsqrtf(var + 1e-5f);
    size_t o0 = (size_t)drow*EMB;
#pragma unroll
    for (int r=0;r<3;r++){
        int e = tid + r*256;
        float v = (r==0)?v0:((r==1)?v1:v2);
        float y = (v-mu)*inv*g[e] + b[e];
        yh[o0+e] = __float2half_rn(y);
    }
}

__global__ void __launch_bounds__(256) ln_f32(const float* __restrict__ x,
        const float* __restrict__ g, const float* __restrict__ b,
        float* __restrict__ y)
{
    int row = blockIdx.x;
    const float* xr = x + (size_t)row*EMB;
    float* yr = y + (size_t)row*EMB;
    int tid = threadIdx.x;
    float v0=xr[tid], v1=xr[tid+256], v2=xr[tid+512];
    float s  = v0+v1+v2;
    float s2 = v0*v0+v1*v1+v2*v2;
    __shared__ float red[2][8];
    int lane=tid&31, wid=tid>>5;
#pragma unroll
    for(int o=16;o;o>>=1){ s+=__shfl_xor_sync(0xffffffffu,s,o); s2+=__shfl_xor_sync(0xffffffffu,s2,o); }
    if(!lane){ red[0][wid]=s; red[1][wid]=s2; }
    __syncthreads();
    s=0.f; s2=0.f;
#pragma unroll
    for (int i=0;i<8;i++){ s+=red[0][i]; s2+=red[1][i]; }
    float mu = s * (1.f/768.f);
    float var = s2*(1.f/768.f) - mu*mu;
    float inv = rsqrtf(var + 1e-5f);
    yr[tid]     = (v0-mu)*inv*g[tid]     + b[tid];
    yr[tid+256] = (v1-mu)*inv*g[tid+256] + b[tid+256];
    yr[tid+512] = (v2-mu)*inv*g[tid+512] + b[tid+512];
}

/* ---------------- im2col -> fp16 plane ---------------- */
__global__ void im2col_split(const float* __restrict__ x, __half* __restrict__ ph)
{
    int idx = blockIdx.x*blockDim.x + threadIdx.x;
    if (idx >= MROWS*EMB) return;
    int r = idx / EMB, col = idx % EMB;
    int b = r / NTOK, t = r % NTOK;
    float v = 0.f;
    if (t > 0){
        int pp = t-1;
        int py = pp/14, px = pp%14;
        int c = col >> 8, phh = (col>>4)&15, pw = col&15;
        v = x[(((size_t)b*3 + c)*224 + py*16+phh)*224 + px*16+pw];
    }
    ph[idx] = __float2half_rn(v);
}

__global__ void fill_cls(const float* __restrict__ cls, const float* __restrict__ ccls,
                         float* __restrict__ xx)
{
    int b = blockIdx.x, tid=threadIdx.x;
#pragma unroll
    for (int r=0;r<3;r++){
        int e = tid+r*256;
        xx[(size_t)b*NTOK*EMB+e]              = cls[e];
        xx[((size_t)MROWS + b*NTOK)*EMB+e]    = ccls[e];
    }
}

__global__ void build_qkvb(const float* __restrict__ qb, const float* __restrict__ vb,
                           const float* __restrict__ cqb, const float* __restrict__ cvb,
                           float* __restrict__ outv, float* __restrict__ coutv)
{
    int idx = blockIdx.x*blockDim.x+threadIdx.x;
    if (idx >= NLAYER*E3) return;
    int l = idx / E3, j = idx % E3;
    float v=0.f, cv=0.f;
    if (j < EMB)        { v=qb[l*EMB+j];        cv=cqb[l*EMB+j]; }
    else if (j >= 2*EMB){ v=vb[l*EMB+j-2*EMB];  cv=cvb[l*EMB+j-2*EMB]; }
    outv[idx]=v; coutv[idx]=cv;
}

/* -------- attention preprocess: pack Qp, Kp, Vt, cVt + stats ---------- */
__global__ void __launch_bounds__(256) attn_pre(const __half* __restrict__ qkv,
   __half* __restrict__ qph, __half* __restrict__ kp,
   __half* __restrict__ vt, __half* __restrict__ cvt,
   float* __restrict__ qs2, float* __restrict__ ks2,
   float* __restrict__ cqsum, float* __restrict__ cksum)
{
    int grp = threadIdx.x >> 6;
    int d   = threadIdx.x & 63;
    int idx = blockIdx.x*4 + grp;
    int t  = idx % NTOK;
    int bh = idx / NTOK;
    int h  = bh % NHEAD;
    int b  = bh / NHEAD;
    size_t mb = ((size_t)(b*NTOK+t))*E3 + h*HD + d;
    size_t cb = ((size_t)(MROWS + b*NTOK+t))*E3 + h*HD + d;
    float q  = __half2float(qkv[mb])*QSCALE;
    float k  = __half2float(qkv[mb+EMB]);
    float v  = __half2float(qkv[mb+2*EMB]);
    float cq = __half2float(qkv[cb]);
    float ck = __half2float(qkv[cb+EMB]);
    float cv = __half2float(qkv[cb+2*EMB]);
    float sq = sqrtf(fmaxf(cq,1e-24f));
    float sk = sqrtf(fmaxf(ck,1e-24f));

    size_t qrow = ((size_t)bh*TP + t)*128;
    qph[qrow+d]    = __float2half_rn(q);
    qph[qrow+64+d] = __float2half_rn(sq);
    kp[qrow+d]    = __float2half_rn(k);
    kp[qrow+64+d] = __float2half_rn(sk);
    vt [((size_t)bh*64 + d)*MP + t] = __float2half_rn(v);
    cvt[((size_t)bh*64 + d)*MP + t] = __float2half_rn(cv);

    float r0=q*q, r1=k*k, r2=cq, r3=ck;
#pragma unroll
    for(int off=16;off;off>>=1){
        r0+=__shfl_xor_sync(0xffffffffu,r0,off);
        r1+=__shfl_xor_sync(0xffffffffu,r1,off);
        r2+=__shfl_xor_sync(0xffffffffu,r2,off);
        r3+=__shfl_xor_sync(0xffffffffu,r3,off);
    }
    __shared__ float sh[4][4][2];
    int lane = threadIdx.x & 31;
    int wno = (threadIdx.x >> 5) & 1;
    if(!lane){ sh[grp][0][wno]=r0; sh[grp][1][wno]=r1; sh[grp][2][wno]=r2; sh[grp][3][wno]=r3; }
    __syncthreads();
    if (d==0){
        qs2[idx]  =sh[grp][0][0]+sh[grp][0][1];
        ks2[idx]  =sh[grp][1][0]+sh[grp][1][1];
        cqsum[idx]=sh[grp][2][0]+sh[grp][2][1];
        cksum[idx]=sh[grp][3][0]+sh[grp][3][1];
    }
}

/* -------- score MMA: sdot[bh][n][m] = Qp[n]·Kp[m], K=128, 1 product --- */
#define SPITCH 68
#define SC_SMEM (2*64*SPITCH*4)
__global__ void __launch_bounds__(256) score_mma(
    const __half* __restrict__ qph,
    const __half* __restrict__ kp, __half* __restrict__ sdot)
{
    extern __shared__ uint32_t sm[];
    uint32_t* sQ = sm;
    uint32_t* sK = sm + 64*SPITCH;
    const int tid = threadIdx.x;
    const int lane = tid & 31, wid = tid >> 5;
    const int wm = wid >> 2, wn = wid & 3;
    const int g = lane >> 2, tig = lane & 3;
    const int bh = blockIdx.z;
    const int n0 = blockIdx.y * 64;
    const int m0 = blockIdx.x * 64;
    const uint32_t sb = s2u(sm);
    const uint32_t* gQ = (const uint32_t*)qph;
    const uint32_t* gK = (const uint32_t*)kp;

#pragma unroll
    for (int i=0;i<4;i++){
        int j = tid + i*256;
        int row = j >> 4, c = (j & 15)*4;
        uint32_t so = (uint32_t)(row*SPITCH + c)*4;
        size_t qa = ((size_t)bh*TP + n0 + row)*64 + c;
        size_t ka = ((size_t)bh*TP + m0 + row)*64 + c;
        cpa16(sb + so,                gQ + qa);
        cpa16(sb + 64*SPITCH*4 + so,  gK + ka);
    }
    asm volatile("cp.async.commit_group;\n");
    asm volatile("cp.async.wait_group 0;\n" ::: "memory");
    __syncthreads();

    float acc[2][2][4];
#pragma unroll
    for (int a=0;a<2;a++)
#pragma unroll
        for (int b=0;b<2;b++)
#pragma unroll
            for (int c=0;c<4;c++) acc[a][b][c]=0.f;

#pragma unroll
    for (int s=0;s<8;s++){
        int kc = s*8 + tig;
        uint32_t b0[2], b1[2];
#pragma unroll
        for (int nt=0;nt<2;nt++){
            int rb = wn*16 + nt*8 + g;
            b0[nt]=sK[rb*SPITCH+kc]; b1[nt]=sK[rb*SPITCH+kc+4];
        }
#pragma unroll
        for (int mt=0;mt<2;mt++){
            int r = wm*32 + mt*16 + g;
            uint32_t a0=sQ[r*SPITCH+kc],     a1=sQ[(r+8)*SPITCH+kc];
            uint32_t a2=sQ[r*SPITCH+kc+4],   a3=sQ[(r+8)*SPITCH+kc+4];
#pragma unroll
            for (int nt=0;nt<2;nt++){
                mma16816(acc[mt][nt], a0,a1,a2,a3, b0[nt],b1[nt]);
            }
        }
    }

#pragma unroll
    for (int mt=0;mt<2;mt++){
#pragma unroll
        for (int hf=0;hf<2;hf++){
            int n = n0 + wm*32 + mt*16 + g + hf*8;
#pragma unroll
            for (int nt=0;nt<2;nt++){
                int m = m0 + wn*16 + nt*8 + tig*2;
                __half2 hv;
                hv.x = __float2half_rn(acc[mt][nt][hf*2]);
                hv.y = __float2half_rn(acc[mt][nt][hf*2+1]);
                *(__half2*)&sdot[((size_t)bh*TP + n)*TP + m] = hv;
            }
        }
    }
}

/* -------- softmax: w -> sigmoid -> +relb -> softmax -> attn planes ----- */
__global__ void __launch_bounds__(256) attn_softmax(
    const __half* __restrict__ sdot,
    const float* __restrict__ qs2, const float* __restrict__ cqsum,
    const float* __restrict__ ks2, const float* __restrict__ cksum,
    const float* __restrict__ relb,
    __half* __restrict__ ah, __half* __restrict__ a2h)
{
    __shared__ float ssc[16][MP];
    int bh = blockIdx.y;
    int hh = bh % NHEAD;
    int n0 = blockIdx.x * 16;
    int tid = threadIdx.x;
    int wid = tid>>5, lane = tid&31;

    for (int r = wid; r < 16; r += 8){
        int n = n0 + r;
        if (n >= NTOK) continue;
        float rq = qs2[bh*NTOK+n] + cqsum[bh*NTOK+n];
        const __half* srow = sdot + ((size_t)bh*TP + n)*TP;
        float mx = -1e30f;
        for (int m=lane; m<NTOK; m+=32){
            float w = -2.f*__half2float(srow[m]) + rq + ks2[bh*NTOK+m] + cksum[bh*NTOK+m];
            float s = 1.f/(1.f+expf(w - 1e-24f));
            float val = s + relb[((size_t)hh*NTOK + n)*NTOK + m];
            ssc[r][m] = val;
            mx = fmaxf(mx, val);
        }
#pragma unroll
        for (int o=16;o;o>>=1) mx = fmaxf(mx, __shfl_xor_sync(0xffffffffu,mx,o));
        float sum = 0.f;
        for (int m=lane; m<NTOK; m+=32){
            float e = expf(ssc[r][m]-mx); ssc[r][m]=e; sum+=e;
        }
#pragma unroll
        for (int o=16;o;o>>=1) sum += __shfl_xor_sync(0xffffffffu,sum,o);
        float inv = 1.f/sum;
        size_t ob = ((size_t)bh*TP + n)*MP;
        for (int m=lane; m<NTOK; m+=32){
            float a = ssc[r][m]*inv;
            ah[ob+m]  = __float2half_rn(a);
            a2h[ob+m] = __float2half_rn(a*a);
        }
    }
}

/* -------- AV MMA: ctx[n][d] = attn·Vt, K=208, single product ----------- */
#define AVPITCH 108
#define AV_SMEM (2*64*AVPITCH*4)
__global__ void __launch_bounds__(256) av_mma(
    const __half* __restrict__ ah, const __half* __restrict__ a2h,
    const __half* __restrict__ vt, const __half* __restrict__ cvt,
    __half* __restrict__ ctx)
{
    extern __shared__ uint32_t sm[];
    uint32_t* sAh = sm;
    uint32_t* sB  = sm + 64*AVPITCH;
    const int tid = threadIdx.x;
    const int lane = tid & 31, wid = tid >> 5;
    const int wm = wid >> 2, wn = wid & 3;
    const int g = lane >> 2, tig = lane & 3;
    const int n0 = blockIdx.x * 64;
    const int bh = blockIdx.y;
    const int path = blockIdx.z;
    const uint32_t sb = s2u(sm);
    const uint32_t* gAh = (const uint32_t*)(path ? a2h : ah);
    const uint32_t* gB  = (const uint32_t*)(path ? cvt : vt);

#pragma unroll
    for (int i=0;i<7;i++){
        int j = tid + i*256;
        if (j < 1664){
            int row = j / 26, c = (j % 26)*4;
            uint32_t so = (uint32_t)(row*AVPITCH + c)*4;
            size_t aa = ((size_t)bh*TP + n0 + row)*104 + c;
            size_t ba = ((size_t)bh*64 + row)*104 + c;
            cpa16(sb + so,                 gAh + aa);
            cpa16(sb + 64*AVPITCH*4 + so,  gB  + ba);
        }
    }
    asm volatile("cp.async.commit_group;\n");
    asm volatile("cp.async.wait_group 0;\n" ::: "memory");
    __syncthreads();

    float acc[2][2][4];
#pragma unroll
    for (int a=0;a<2;a++)
#pragma unroll
        for (int b=0;b<2;b++)
#pragma unroll
            for (int c=0;c<4;c++) acc[a][b][c]=0.f;

    for (int s=0;s<13;s++){
        int kc = s*8 + tig;
        uint32_t b0[2], b1[2];
#pragma unroll
        for (int nt=0;nt<2;nt++){
            int rb = wn*16 + nt*8 + g;
            b0[nt]=sB[rb*AVPITCH+kc]; b1[nt]=sB[rb*AVPITCH+kc+4];
        }
#pragma unroll
        for (int mt=0;mt<2;mt++){
            int r = wm*32 + mt*16 + g;
            uint32_t a0=sAh[r*AVPITCH+kc],     a1=sAh[(r+8)*AVPITCH+kc];
            uint32_t a2=sAh[r*AVPITCH+kc+4],   a3=sAh[(r+8)*AVPITCH+kc+4];
#pragma unroll
            for (int nt=0;nt<2;nt++){
                mma16816(acc[mt][nt], a0,a1,a2,a3, b0[nt],b1[nt]);
            }
        }
    }

    const int b = bh / NHEAD;
    const int hh = bh % NHEAD;
#pragma unroll
    for (int mt=0;mt<2;mt++){
#pragma unroll
        for (int hf=0;hf<2;hf++){
            int n = n0 + wm*32 + mt*16 + g + hf*8;
            if (n >= NTOK) continue;
            size_t row = (size_t)(path*MPAD + b*NTOK + n)*EMB + hh*64;
#pragma unroll
            for (int nt=0;nt<2;nt++){
                int d0 = wn*16 + nt*8 + tig*2;
                __half2 hv;
                hv.x = __float2half_rn(acc[mt][nt][hf*2]);
                hv.y = __float2half_rn(acc[mt][nt][hf*2+1]);
                *(__half2*)(ctx + row + d0) = hv;
            }
        }
    }
}

/* ------------------------------ tail ---------------------------------- */
__global__ void __launch_bounds__(256) pool_kernel(const float* __restrict__ xx, float* __restrict__ pool)
{
    int b = blockIdx.x;
    int tid=threadIdx.x;
#pragma unroll
    for (int r=0;r<3;r++){
        int e = tid + r*256;
        float s=0.f;
        for (int n=1;n<NTOK;n++) s += xx[((size_t)(b*NTOK+n))*EMB+e];
        pool[b*EMB+e]=s*(1.f/196.f);
    }
}

__global__ void head_kernel(const float* __restrict__ t, const float* __restrict__ w,
                            const float* __restrict__ hb, float* __restrict__ out)
{
    int idx = blockIdx.x*blockDim.x + threadIdx.x;
    if (idx >= BATCH*NCLS) return;
    int b = idx/NCLS, c = idx%NCLS;
    const float* tr = t + b*EMB;
    const float* wr = w + (size_t)c*EMB;
    float s = hb[c];
    for (int e=0;e<EMB;e+=4){
        float4 tv=*(const float4*)(tr+e);
        float4 wv=*(const float4*)(wr+e);
        s += tv.x*wv.x+tv.y*wv.y+tv.z*wv.z+tv.w*wv.w;
    }
    out[idx]=s;
}

/* ------------------------------ host ---------------------------------- */
extern "C" void kernel_launch(void* const* d_in, const int* in_sizes, int n_in,
                              void* d_out, int out_size)
{
    const float* x        = (const float*)d_in[0];
    const float* relb     = (const float*)d_in[1];
    const float* patch_w  = (const float*)d_in[2];
    const float* patch_b  = (const float*)d_in[3];
    const float* cpatch_w = (const float*)d_in[4];
    const float* cpatch_b = (const float*)d_in[5];
    const float* cls      = (const float*)d_in[6];
    const float* ccls     = (const float*)d_in[7];
    const float* n1g      = (const float*)d_in[8];
    const float* n1b      = (const float*)d_in[9];
    const float* qkvw     = (const float*)d_in[10];
    const float* qb       = (const float*)d_in[11];
    const float* vb       = (const float*)d_in[12];
    const float* cqb      = (const float*)d_in[13];
    const float* cvb      = (const float*)d_in[14];
    const float* projw    = (const float*)d_in[15];
    const float* projb    = (const float*)d_in[16];
    const float* cprojw   = (const float*)d_in[17];
    const float* cprojb   = (const float*)d_in[18];
    const float* gamma1   = (const float*)d_in[19];
    const float* gamma2   = (const float*)d_in[20];
    const float* n2g      = (const float*)d_in[21];
    const float* n2b      = (const float*)d_in[22];
    const float* fc1w     = (const float*)d_in[23];
    const float* fc1b     = (const float*)d_in[24];
    const float* fc2w     = (const float*)d_in[25];
    const float* fc2b     = (const float*)d_in[26];
    const float* fng      = (const float*)d_in[27];
    const float* fnb      = (const float*)d_in[28];
    const float* headw    = (const float*)d_in[29];
    const float* headb    = (const float*)d_in[30];
    float* out = (float*)d_out;

    static int attr_set = 0;
    if (!attr_set){
        cudaFuncSetAttribute(gemm_h, cudaFuncAttributeMaxDynamicSharedMemorySize, GEMM_SMEM);
        cudaFuncSetAttribute(score_mma, cudaFuncAttributeMaxDynamicSharedMemorySize, SC_SMEM);
        cudaFuncSetAttribute(av_mma, cudaFuncAttributeMaxDynamicSharedMemorySize, AV_SMEM);
        attr_set = 1;
    }

    __half *w,*pat,*tn,*ctx,*hbuf,*qkvh,*qph,*kp,*vt,*cvt,*sdot,*ahp,*a2hp;
    float *p_x,*p_qs2,*p_ks2,*p_cqsum,*p_cksum,*p_qkvb,*p_cqkvb,*p_pool,*p_pooln;
    cudaGetSymbolAddress((void**)&w, g_w);
    cudaGetSymbolAddress((void**)&pat, g_pat);
    cudaGetSymbolAddress((void**)&tn, g_tn);
    cudaGetSymbolAddress((void**)&ctx, g_ctx);
    cudaGetSymbolAddress((void**)&hbuf, g_h);
    cudaGetSymbolAddress((void**)&qkvh, g_qkv);
    cudaGetSymbolAddress((void**)&qph, g_qph);
    cudaGetSymbolAddress((void**)&kp,  g_kp);
    cudaGetSymbolAddress((void**)&vt,  g_vt);
    cudaGetSymbolAddress((void**)&cvt, g_cvt);
    cudaGetSymbolAddress((void**)&sdot,g_sdot);
    cudaGetSymbolAddress((void**)&ahp, g_ah);
    cudaGetSymbolAddress((void**)&a2hp,g_a2h);
    cudaGetSymbolAddress((void**)&p_x,    g_x);
    cudaGetSymbolAddress((void**)&p_qs2,  g_qs2);
    cudaGetSymbolAddress((void**)&p_ks2,  g_ks2);
    cudaGetSymbolAddress((void**)&p_cqsum,g_cqsum);
    cudaGetSymbolAddress((void**)&p_cksum,g_cksum);
    cudaGetSymbolAddress((void**)&p_qkvb, g_qkvb);
    cudaGetSymbolAddress((void**)&p_cqkvb,g_cqkvb);
    cudaGetSymbolAddress((void**)&p_pool, g_pool);
    cudaGetSymbolAddress((void**)&p_pooln,g_pooln);

    auto wsp = [&](const float* src, size_t off, size_t cnt){
        size_t n4 = cnt/4;
        size_t n8 = n4/2;
        unsigned blocks = (unsigned)((n8 + 1023)/1024);
        wsplit_h<<<blocks,256>>>((const float4*)src, w+off, n4);
    };
    wsp(patch_w,  OFF_PW,    589824);
    wsp(cpatch_w, OFF_CPW,   589824);
    wsp(qkvw,     OFF_QKV,   21233664);
    wsp(projw,    OFF_PROJ,  7077888);
    wsp(cprojw,   OFF_CPROJ, 7077888);
    wsp(fc1w,     OFF_FC1,   28311552);
    wsp(fc2w,     OFF_FC2,   28311552);

    build_qkvb<<<(NLAYER*E3+255)/256,256>>>(qb,vb,cqb,cvb,p_qkvb,p_cqkvb);
    im2col_split<<<(MROWS*EMB+255)/256,256>>>(x, pat);

    gemm_h<<<dim3(EMB/128,13,2),256,GEMM_SMEM>>>(
        pat, w+OFF_PW, w+OFF_CPW,
        patch_b, cpatch_b, nullptr, p_x, nullptr, EMB, EMB, EPI_BIAS, EPI_BIAS, 1);
    fill_cls<<<BATCH,256>>>(cls, ccls, p_x);

    for (int i=0;i<NLAYER;i++){
        size_t qkv_o  = OFF_QKV   + (size_t)i*E3*EMB;
        size_t proj_o = OFF_PROJ  + (size_t)i*EMB*EMB;
        size_t cprj_o = OFF_CPROJ + (size_t)i*EMB*EMB;
        size_t fc1_o  = OFF_FC1   + (size_t)i*(size_t)MLPD*EMB;
        size_t fc2_o  = OFF_FC2   + (size_t)i*(size_t)EMB*MLPD;

        ln_split<<<2*MROWS,256>>>(p_x, n1g+i*EMB, n1b+i*EMB, tn);
        gemm_h<<<dim3(E3/128,13,2),256,GEMM_SMEM>>>(
            tn, w+qkv_o, w+qkv_o,
            p_qkvb+i*E3, p_cqkvb+i*E3, nullptr, nullptr, qkvh,
            E3, EMB, EPI_QKVH, EPI_CQKVH, 0);

        attn_pre<<<BATCH*NHEAD*NTOK/4,256>>>(qkvh, qph,kp,vt,cvt,
                                             p_qs2,p_ks2,p_cqsum,p_cksum);
        score_mma<<<dim3(4,4,BH),256,SC_SMEM>>>(qph,kp,sdot);
        attn_softmax<<<dim3(13,BH),256>>>(sdot,p_qs2,p_cqsum,p_ks2,p_cksum,relb,
                                          ahp,a2hp);
        av_mma<<<dim3(4,BH,2),256,AV_SMEM>>>(ahp,a2hp,vt,cvt,ctx);

        gemm_h<<<dim3(EMB/128,13,2),256,GEMM_SMEM>>>(
            ctx, w+proj_o, w+cprj_o,
            projb+i*EMB, cprojb+i*EMB, gamma1+i*EMB, p_x, nullptr,
            EMB, EMB, EPI_RES, EPI_RES, 0);

        ln_split<<<2*MROWS,256>>>(p_x, n2g+i*EMB, n2b+i*EMB, tn);
        gemm_h<<<dim3(MLPD/128,13,2),256,GEMM_SMEM>>>(
            tn, w+fc1_o, w+fc1_o,
            fc1b+i*MLPD, fc1b+i*MLPD, nullptr, nullptr, hbuf,
            MLPD, EMB, EPI_GELU, EPI_GELU, 0);
        gemm_h<<<dim3(EMB/128,13,2),256,GEMM_SMEM>>>(
            hbuf, w+fc2_o, w+fc2_o,
            fc2b+i*EMB, fc2b+i*EMB, gamma2+i*EMB, p_x, nullptr,
            EMB, MLPD, EPI_RES, EPI_RES, 0);
    }

    pool_kernel<<<BATCH,256>>>(p_x, p_pool);
    ln_f32<<<BATCH,256>>>(p_pool, fng, fnb, p_pooln);
    head_kernel<<<(BATCH*NCLS+255)/256,256>>>(p_pooln, headw, headb, out);
}

// round 17
// speedup vs baseline: 1.0837x; 1.0090x over previous
#include <cuda_runtime.h>
#include <cuda_fp16.h>
#include <stdint.h>
#include <math.h>

#define BATCH 8
#define EMB 768
#define NHEAD 12
#define NLAYER 12
#define HD 64
#define NTOK 197
#define MROWS (BATCH*NTOK)   /* 1576 */
#define MPAD 1664            /* 13*128 */
#define E3 2304
#define MLPD 3072
#define QSCALE 0.125f
#define NCLS 1000
#define BH 96                /* BATCH*NHEAD */
#define TP 256               /* padded tokens for mma M/N */
#define MP 208               /* padded m (K dim of AV) */
#define RELBN (NHEAD*NTOK*NTOK)

enum { EPI_BIAS=0, EPI_GELU=1, EPI_RES=2, EPI_QKVH=3, EPI_CQKVH=4 };

/* ---------------- weight plane offsets (elements) ---------------- */
#define OFF_PW    0ULL
#define OFF_CPW   589824ULL
#define OFF_QKV   1179648ULL
#define OFF_PROJ  22413312ULL
#define OFF_CPROJ 29491200ULL
#define OFF_FC1   36569088ULL
#define OFF_FC2   64880640ULL
#define WTOT      93192192ULL

/* ------------------------------ scratch ------------------------------ */
__device__ __half g_w[WTOT];

__device__ __half g_pat[MPAD*EMB];
__device__ __half g_tn [2*MPAD*EMB];
__device__ __half g_ctx[2*MPAD*EMB];
__device__ __half g_h  [2*(size_t)MPAD*MLPD];

__device__ float g_x[2*MROWS*EMB];
__device__ __half g_qkv[2*(size_t)MROWS*E3];

/* attention buffers (zero-initialized; pad regions never written) */
__device__ __half g_qph[(size_t)BH*TP*128];
__device__ __half g_kp [(size_t)BH*TP*128];
__device__ __half g_vt [(size_t)BH*64*MP];
__device__ __half g_cvt[(size_t)BH*64*MP];
__device__ __half g_sdot[(size_t)BH*TP*TP];
__device__ __half g_ah [(size_t)BH*TP*MP];
__device__ __half g_relbh[RELBN];

__device__ float g_qstat[BH*NTOK];
__device__ float g_kstat[BH*NTOK];
__device__ float g_qkvb[NLAYER*E3];
__device__ float g_cqkvb[NLAYER*E3];
__device__ float g_pool[BATCH*EMB];
__device__ float g_pooln[BATCH*EMB];

/* ------------------------------ helpers ------------------------------ */
__device__ __forceinline__ uint32_t s2u(const void* p){
    return (uint32_t)__cvta_generic_to_shared(p);
}
__device__ __forceinline__ void cpa16(uint32_t dst, const void* src){
    asm volatile("cp.async.cg.shared.global [%0], [%1], 16;\n" :: "r"(dst), "l"(src));
}
__device__ __forceinline__ void mma16816(float* c, uint32_t a0,uint32_t a1,uint32_t a2,uint32_t a3,
                                         uint32_t b0,uint32_t b1){
    asm volatile("mma.sync.aligned.m16n8k16.row.col.f32.f16.f16.f32 "
        "{%0,%1,%2,%3},{%4,%5,%6,%7},{%8,%9},{%0,%1,%2,%3};\n"
        : "+f"(c[0]),"+f"(c[1]),"+f"(c[2]),"+f"(c[3])
        : "r"(a0),"r"(a1),"r"(a2),"r"(a3),"r"(b0),"r"(b1));
}

/* ---------------- fp16 GEMM: C[M,N] = A[M,K]*B[N,K]^T, 3-stage -------- */
#define APITCH 20
#define PLANE_U32 (128*APITCH)
#define STAGE_U32 (2*PLANE_U32)
#define GEMM_SMEM (3*STAGE_U32*4)

__global__ void __launch_bounds__(256)
gemm_h(const __half* __restrict__ A,
       const __half* __restrict__ B0, const __half* __restrict__ B1,
       const float* __restrict__ bias0, const float* __restrict__ bias1,
       const float* __restrict__ gamma,
       float* __restrict__ C, __half* __restrict__ Ch,
       int N, int K, int epi0, int epi1, int aShared)
{
    extern __shared__ uint32_t smem[];
    const int tid = threadIdx.x;
    const int lane = tid & 31, wid = tid >> 5;
    const int wm = wid >> 2, wn = wid & 3;
    const int g = lane >> 2, tig = lane & 3;
    const int half_ = blockIdx.z;
    const int lmBase = blockIdx.y * 128;
    const int aBase = (aShared ? 0 : half_*MPAD) + lmBase;
    const int bn = blockIdx.x * 128;
    const int K2 = K >> 1;
    const __half* B = half_ ? B1 : B0;
    const float* bias = half_ ? bias1 : bias0;
    const int epi = half_ ? epi1 : epi0;

    const uint32_t* gA = (const uint32_t*)A;
    const uint32_t* gB = (const uint32_t*)B;
    const uint32_t sbase_u = s2u(smem);

    float acc[4][4][4];
#pragma unroll
    for (int a=0;a<4;a++)
#pragma unroll
        for (int b=0;b<4;b++)
#pragma unroll
            for (int c=0;c<4;c++) acc[a][b][c]=0.f;

    const int KT = K >> 5;

    auto fill = [&](int buf, int kt){
        uint32_t sd = sbase_u + (uint32_t)buf*STAGE_U32*4;
        int kc0 = kt*16;
#pragma unroll
        for (int i=0;i<2;i++){
            int t = tid + i*256;
            int row = t >> 2, ch = (t & 3) * 4;
            size_t ga = (size_t)(aBase+row)*K2 + kc0 + ch;
            size_t gb = (size_t)(bn + row)*K2 + kc0 + ch;
            uint32_t so = (uint32_t)(row*APITCH + ch)*4;
            cpa16(sd + so,                 gA + ga);
            cpa16(sd + PLANE_U32*4 + so,   gB + gb);
        }
        asm volatile("cp.async.commit_group;\n");
    };

    fill(0, 0);
    if (KT > 1) fill(1, 1);

    for (int kt=0; kt<KT; kt++){
        int buf = kt % 3;
        if (kt+2 < KT){
            fill((kt+2)%3, kt+2);
            asm volatile("cp.async.wait_group 2;\n" ::: "memory");
        } else if (kt+1 < KT){
            asm volatile("cp.async.wait_group 1;\n" ::: "memory");
        } else {
            asm volatile("cp.async.wait_group 0;\n" ::: "memory");
        }
        __syncthreads();

        const uint32_t* sA = smem + buf*STAGE_U32;
        const uint32_t* sB = sA + PLANE_U32;

#pragma unroll
        for (int ks=0; ks<2; ks++){
            const int kc = ks*8 + tig;
            uint32_t bh[4][2];
#pragma unroll
            for (int nt=0;nt<4;nt++){
                int n = wn*32 + nt*8 + g;
                bh[nt][0]=sB[n*APITCH+kc]; bh[nt][1]=sB[n*APITCH+kc+4];
            }
#pragma unroll
            for (int mt=0;mt<4;mt++){
                int m = wm*64 + mt*16 + g;
                uint32_t a0=sA[m*APITCH+kc],     a1=sA[(m+8)*APITCH+kc];
                uint32_t a2=sA[m*APITCH+kc+4],   a3=sA[(m+8)*APITCH+kc+4];
#pragma unroll
                for (int nt=0;nt<4;nt++){
                    mma16816(acc[mt][nt], a0,a1,a2,a3, bh[nt][0],bh[nt][1]);
                }
            }
        }
        __syncthreads();
    }

#pragma unroll
    for (int mt=0;mt<4;mt++){
        int lm0 = lmBase + wm*64 + mt*16 + g;
#pragma unroll
        for (int hf=0; hf<2; hf++){
            int lm = lm0 + hf*8;
            if (lm >= MROWS) continue;
            size_t crow = (size_t)(half_*MROWS + lm)*N;
            size_t prow = (size_t)(half_*MPAD  + lm)*N;
#pragma unroll
            for (int nt=0;nt<4;nt++){
                int gn = bn + wn*32 + nt*8 + tig*2;
                float z0 = acc[mt][nt][hf*2+0];
                float z1 = acc[mt][nt][hf*2+1];
                if (bias){ z0 += bias[gn]; z1 += bias[gn+1]; }
                if (epi == EPI_BIAS){
                    *(float2*)(C + crow + gn) = make_float2(z0, z1);
                } else if (epi == EPI_GELU){
                    float o0 = 0.5f*z0*(1.f+erff(z0*0.70710678118f));
                    float o1 = 0.5f*z1*(1.f+erff(z1*0.70710678118f));
                    __half2 hv;
                    hv.x = __float2half_rn(o0); hv.y = __float2half_rn(o1);
                    *(__half2*)(Ch + prow + gn) = hv;
                } else if (epi == EPI_RES){
                    float2 old = *(const float2*)(C + crow + gn);
                    float o0 = old.x + gamma[gn]*z0;
                    float o1 = old.y + gamma[gn+1]*z1;
                    *(float2*)(C + crow + gn) = make_float2(o0,o1);
                } else if (epi == EPI_QKVH){
                    __half2 hv;
                    hv.x = __float2half_rn(z0); hv.y = __float2half_rn(z1);
                    *(__half2*)(Ch + crow + gn) = hv;
                } else { /* EPI_CQKVH: elu+1 then fp16 */
                    float o0 = (z0>0.f)? z0+1.f : expf(z0);
                    float o1 = (z1>0.f)? z1+1.f : expf(z1);
                    __half2 hv;
                    hv.x = __float2half_rn(o0); hv.y = __float2half_rn(o1);
                    *(__half2*)(Ch + crow + gn) = hv;
                }
            }
        }
    }
}

/* ---------------- weight -> fp16 (grid-stride, 32B in / 16B out) ------ */
__global__ void wsplit_h(const float4* __restrict__ src, __half* __restrict__ hi, size_t n4)
{
    size_t n8 = n4 >> 1;
    size_t stride = (size_t)gridDim.x * 256;
    for (size_t i = (size_t)blockIdx.x*256 + threadIdx.x; i < n8; i += stride){
        float4 f0 = src[2*i], f1 = src[2*i+1];
        __half2 h0, h1, h2, h3;
        h0.x = __float2half_rn(f0.x); h0.y = __float2half_rn(f0.y);
        h1.x = __float2half_rn(f0.z); h1.y = __float2half_rn(f0.w);
        h2.x = __float2half_rn(f1.x); h2.y = __float2half_rn(f1.y);
        h3.x = __float2half_rn(f1.z); h3.y = __float2half_rn(f1.w);
        uint4 u;
        u.x = *(uint32_t*)&h0; u.y = *(uint32_t*)&h1;
        u.z = *(uint32_t*)&h2; u.w = *(uint32_t*)&h3;
        *(uint4*)(hi + 8*i) = u;
    }
}

/* ---------------- relb -> fp16 (grid-stride) ---------------- */
__global__ void relb_h(const float* __restrict__ src, __half* __restrict__ dst, int n)
{
    int stride = gridDim.x * 256;
    for (int i = blockIdx.x*256 + threadIdx.x; i < n; i += stride)
        dst[i] = __float2half_rn(src[i]);
}

/* ---------------- merged LayerNorm -> fp16 plane ---------------- */
__global__ void __launch_bounds__(256) ln_split(const float* __restrict__ x,
        const float* __restrict__ g, const float* __restrict__ b,
        __half* __restrict__ yh)
{
    int row = blockIdx.x;
    int drow = (row < MROWS) ? row : row + (MPAD - MROWS);
    const float* xr = x + (size_t)row*EMB;
    int tid = threadIdx.x;
    float v0=xr[tid], v1=xr[tid+256], v2=xr[tid+512];
    float s  = v0+v1+v2;
    float s2 = v0*v0+v1*v1+v2*v2;
    __shared__ float red[2][8];
    int lane=tid&31, wid=tid>>5;
#pragma unroll
    for(int o=16;o;o>>=1){ s+=__shfl_xor_sync(0xffffffffu,s,o); s2+=__shfl_xor_sync(0xffffffffu,s2,o); }
    if(!lane){ red[0][wid]=s; red[1][wid]=s2; }
    __syncthreads();
    s=0.f; s2=0.f;
#pragma unroll
    for (int i=0;i<8;i++){ s+=red[0][i]; s2+=red[1][i]; }
    float mu = s * (1.f/768.f);
    float var = s2*(1.f/768.f) - mu*mu;
    float inv = rsqrtf(var + 1e-5f);
    size_t o0 = (size_t)drow*EMB;
#pragma unroll
    for (int r=0;r<3;r++){
        int e = tid + r*256;
        float v = (r==0)?v0:((r==1)?v1:v2);
        float y = (v-mu)*inv*g[e] + b[e];
        yh[o0+e] = __float2half_rn(y);
    }
}

__global__ void __launch_bounds__(256) ln_f32(const float* __restrict__ x,
        const float* __restrict__ g, const float* __restrict__ b,
        float* __restrict__ y)
{
    int row = blockIdx.x;
    const float* xr = x + (size_t)row*EMB;
    float* yr = y + (size_t)row*EMB;
    int tid = threadIdx.x;
    float v0=xr[tid], v1=xr[tid+256], v2=xr[tid+512];
    float s  = v0+v1+v2;
    float s2 = v0*v0+v1*v1+v2*v2;
    __shared__ float red[2][8];
    int lane=tid&31, wid=tid>>5;
#pragma unroll
    for(int o=16;o;o>>=1){ s+=__shfl_xor_sync(0xffffffffu,s,o); s2+=__shfl_xor_sync(0xffffffffu,s2,o); }
    if(!lane){ red[0][wid]=s; red[1][wid]=s2; }
    __syncthreads();
    s=0.f; s2=0.f;
#pragma unroll
    for (int i=0;i<8;i++){ s+=red[0][i]; s2+=red[1][i]; }
    float mu = s * (1.f/768.f);
    float var = s2*(1.f/768.f) - mu*mu;
    float inv = rsqrtf(var + 1e-5f);
    yr[tid]     = (v0-mu)*inv*g[tid]     + b[tid];
    yr[tid+256] = (v1-mu)*inv*g[tid+256] + b[tid+256];
    yr[tid+512] = (v2-mu)*inv*g[tid+512] + b[tid+512];
}

/* ---------------- im2col -> fp16 plane ---------------- */
__global__ void im2col_split(const float* __restrict__ x, __half* __restrict__ ph)
{
    int idx = blockIdx.x*blockDim.x + threadIdx.x;
    if (idx >= MROWS*EMB) return;
    int r = idx / EMB, col = idx % EMB;
    int b = r / NTOK, t = r % NTOK;
    float v = 0.f;
    if (t > 0){
        int pp = t-1;
        int py = pp/14, px = pp%14;
        int c = col >> 8, phh = (col>>4)&15, pw = col&15;
        v = x[(((size_t)b*3 + c)*224 + py*16+phh)*224 + px*16+pw];
    }
    ph[idx] = __float2half_rn(v);
}

__global__ void fill_cls(const float* __restrict__ cls, const float* __restrict__ ccls,
                         float* __restrict__ xx)
{
    int b = blockIdx.x, tid=threadIdx.x;
#pragma unroll
    for (int r=0;r<3;r++){
        int e = tid+r*256;
        xx[(size_t)b*NTOK*EMB+e]              = cls[e];
        xx[((size_t)MROWS + b*NTOK)*EMB+e]    = ccls[e];
    }
}

__global__ void build_qkvb(const float* __restrict__ qb, const float* __restrict__ vb,
                           const float* __restrict__ cqb, const float* __restrict__ cvb,
                           float* __restrict__ outv, float* __restrict__ coutv)
{
    int idx = blockIdx.x*blockDim.x+threadIdx.x;
    if (idx >= NLAYER*E3) return;
    int l = idx / E3, j = idx % E3;
    float v=0.f, cv=0.f;
    if (j < EMB)        { v=qb[l*EMB+j];        cv=cqb[l*EMB+j]; }
    else if (j >= 2*EMB){ v=vb[l*EMB+j-2*EMB];  cv=cvb[l*EMB+j-2*EMB]; }
    outv[idx]=v; coutv[idx]=cv;
}

/* -------- attention preprocess: pack Qp, Kp, Vt, cVt + fused stats ---- */
__global__ void __launch_bounds__(256) attn_pre(const __half* __restrict__ qkv,
   __half* __restrict__ qph, __half* __restrict__ kp,
   __half* __restrict__ vt, __half* __restrict__ cvt,
   float* __restrict__ qstat, float* __restrict__ kstat)
{
    int grp = threadIdx.x >> 6;
    int d   = threadIdx.x & 63;
    int idx = blockIdx.x*4 + grp;
    int t  = idx % NTOK;
    int bh = idx / NTOK;
    int h  = bh % NHEAD;
    int b  = bh / NHEAD;
    size_t mb = ((size_t)(b*NTOK+t))*E3 + h*HD + d;
    size_t cb = ((size_t)(MROWS + b*NTOK+t))*E3 + h*HD + d;
    float q  = __half2float(qkv[mb])*QSCALE;
    float k  = __half2float(qkv[mb+EMB]);
    float v  = __half2float(qkv[mb+2*EMB]);
    float cq = __half2float(qkv[cb]);
    float ck = __half2float(qkv[cb+EMB]);
    float cv = __half2float(qkv[cb+2*EMB]);
    float sq = sqrtf(fmaxf(cq,1e-24f));
    float sk = sqrtf(fmaxf(ck,1e-24f));

    size_t qrow = ((size_t)bh*TP + t)*128;
    qph[qrow+d]    = __float2half_rn(q);
    qph[qrow+64+d] = __float2half_rn(sq);
    kp[qrow+d]    = __float2half_rn(k);
    kp[qrow+64+d] = __float2half_rn(sk);
    vt [((size_t)bh*64 + d)*MP + t] = __float2half_rn(v);
    cvt[((size_t)bh*64 + d)*MP + t] = __float2half_rn(cv);

    float r0 = q*q + cq;
    float r1 = k*k + ck;
#pragma unroll
    for(int off=16;off;off>>=1){
        r0+=__shfl_xor_sync(0xffffffffu,r0,off);
        r1+=__shfl_xor_sync(0xffffffffu,r1,off);
    }
    __shared__ float sh[4][2][2];
    int lane = threadIdx.x & 31;
    int wno = (threadIdx.x >> 5) & 1;
    if(!lane){ sh[grp][0][wno]=r0; sh[grp][1][wno]=r1; }
    __syncthreads();
    if (d==0){
        qstat[idx] = sh[grp][0][0]+sh[grp][0][1];
        kstat[idx] = sh[grp][1][0]+sh[grp][1][1];
    }
}

/* -------- score MMA: sdot[bh][n][m] = Qp[n]·Kp[m], K=128, 1 product --- */
#define SPITCH 68
#define SC_SMEM (2*64*SPITCH*4)
__global__ void __launch_bounds__(256) score_mma(
    const __half* __restrict__ qph,
    const __half* __restrict__ kp, __half* __restrict__ sdot)
{
    extern __shared__ uint32_t sm[];
    uint32_t* sQ = sm;
    uint32_t* sK = sm + 64*SPITCH;
    const int tid = threadIdx.x;
    const int lane = tid & 31, wid = tid >> 5;
    const int wm = wid >> 2, wn = wid & 3;
    const int g = lane >> 2, tig = lane & 3;
    const int bh = blockIdx.z;
    const int n0 = blockIdx.y * 64;
    const int m0 = blockIdx.x * 64;
    const uint32_t sb = s2u(sm);
    const uint32_t* gQ = (const uint32_t*)qph;
    const uint32_t* gK = (const uint32_t*)kp;

#pragma unroll
    for (int i=0;i<4;i++){
        int j = tid + i*256;
        int row = j >> 4, c = (j & 15)*4;
        uint32_t so = (uint32_t)(row*SPITCH + c)*4;
        size_t qa = ((size_t)bh*TP + n0 + row)*64 + c;
        size_t ka = ((size_t)bh*TP + m0 + row)*64 + c;
        cpa16(sb + so,                gQ + qa);
        cpa16(sb + 64*SPITCH*4 + so,  gK + ka);
    }
    asm volatile("cp.async.commit_group;\n");
    asm volatile("cp.async.wait_group 0;\n" ::: "memory");
    __syncthreads();

    float acc[2][2][4];
#pragma unroll
    for (int a=0;a<2;a++)
#pragma unroll
        for (int b=0;b<2;b++)
#pragma unroll
            for (int c=0;c<4;c++) acc[a][b][c]=0.f;

#pragma unroll
    for (int s=0;s<8;s++){
        int kc = s*8 + tig;
        uint32_t b0[2], b1[2];
#pragma unroll
        for (int nt=0;nt<2;nt++){
            int rb = wn*16 + nt*8 + g;
            b0[nt]=sK[rb*SPITCH+kc]; b1[nt]=sK[rb*SPITCH+kc+4];
        }
#pragma unroll
        for (int mt=0;mt<2;mt++){
            int r = wm*32 + mt*16 + g;
            uint32_t a0=sQ[r*SPITCH+kc],     a1=sQ[(r+8)*SPITCH+kc];
            uint32_t a2=sQ[r*SPITCH+kc+4],   a3=sQ[(r+8)*SPITCH+kc+4];
#pragma unroll
            for (int nt=0;nt<2;nt++){
                mma16816(acc[mt][nt], a0,a1,a2,a3, b0[nt],b1[nt]);
            }
        }
    }

#pragma unroll
    for (int mt=0;mt<2;mt++){
#pragma unroll
        for (int hf=0;hf<2;hf++){
            int n = n0 + wm*32 + mt*16 + g + hf*8;
#pragma unroll
            for (int nt=0;nt<2;nt++){
                int m = m0 + wn*16 + nt*8 + tig*2;
                __half2 hv;
                hv.x = __float2half_rn(acc[mt][nt][hf*2]);
                hv.y = __float2half_rn(acc[mt][nt][hf*2+1]);
                *(__half2*)&sdot[((size_t)bh*TP + n)*TP + m] = hv;
            }
        }
    }
}

/* -------- softmax: w -> sigmoid -> +relb -> softmax -> attn plane ------ */
__global__ void __launch_bounds__(256) attn_softmax(
    const __half* __restrict__ sdot,
    const float* __restrict__ qstat, const float* __restrict__ kstat,
    const __half* __restrict__ relbh,
    __half* __restrict__ ah)
{
    __shared__ float ssc[16][MP];
    int bh = blockIdx.y;
    int hh = bh % NHEAD;
    int n0 = blockIdx.x * 16;
    int tid = threadIdx.x;
    int wid = tid>>5, lane = tid&31;

    for (int r = wid; r < 16; r += 8){
        int n = n0 + r;
        if (n >= NTOK) continue;
        float rq = qstat[bh*NTOK+n];
        const __half* srow = sdot + ((size_t)bh*TP + n)*TP;
        const __half* rrow = relbh + ((size_t)hh*NTOK + n)*NTOK;
        float mx = -1e30f;
        for (int m=lane; m<NTOK; m+=32){
            float w = -2.f*__half2float(srow[m]) + rq + kstat[bh*NTOK+m];
            float s = 1.f/(1.f+expf(w - 1e-24f));
            float val = s + __half2float(rrow[m]);
            ssc[r][m] = val;
            mx = fmaxf(mx, val);
        }
#pragma unroll
        for (int o=16;o;o>>=1) mx = fmaxf(mx, __shfl_xor_sync(0xffffffffu,mx,o));
        float sum = 0.f;
        for (int m=lane; m<NTOK; m+=32){
            float e = expf(ssc[r][m]-mx); ssc[r][m]=e; sum+=e;
        }
#pragma unroll
        for (int o=16;o;o>>=1) sum += __shfl_xor_sync(0xffffffffu,sum,o);
        float inv = 1.f/sum;
        size_t ob = ((size_t)bh*TP + n)*MP;
        for (int m=lane; m<NTOK; m+=32){
            ah[ob+m] = __float2half_rn(ssc[r][m]*inv);
        }
    }
}

/* -------- AV MMA: ctx[n][d] = attn(^2)·Vt, K=208; squares in smem ------ */
#define AVPITCH 108
#define AV_SMEM (2*64*AVPITCH*4)
__global__ void __launch_bounds__(256) av_mma(
    const __half* __restrict__ ah,
    const __half* __restrict__ vt, const __half* __restrict__ cvt,
    __half* __restrict__ ctx)
{
    extern __shared__ uint32_t sm[];
    uint32_t* sAh = sm;
    uint32_t* sB  = sm + 64*AVPITCH;
    const int tid = threadIdx.x;
    const int lane = tid & 31, wid = tid >> 5;
    const int wm = wid >> 2, wn = wid & 3;
    const int g = lane >> 2, tig = lane & 3;
    const int n0 = blockIdx.x * 64;
    const int bh = blockIdx.y;
    const int path = blockIdx.z;
    const uint32_t sb = s2u(sm);
    const uint32_t* gAh = (const uint32_t*)ah;
    const uint32_t* gB  = (const uint32_t*)(path ? cvt : vt);

#pragma unroll
    for (int i=0;i<7;i++){
        int j = tid + i*256;
        if (j < 1664){
            int row = j / 26, c = (j % 26)*4;
            uint32_t so = (uint32_t)(row*AVPITCH + c)*4;
            size_t aa = ((size_t)bh*TP + n0 + row)*104 + c;
            size_t ba = ((size_t)bh*64 + row)*104 + c;
            cpa16(sb + so,                 gAh + aa);
            cpa16(sb + 64*AVPITCH*4 + so,  gB  + ba);
        }
    }
    asm volatile("cp.async.commit_group;\n");
    asm volatile("cp.async.wait_group 0;\n" ::: "memory");
    __syncthreads();

    if (path){
        /* cov path: square attn weights in smem */
        for (int j = tid; j < 64*104; j += 256){
            int row = j / 104, c = j % 104;
            uint32_t* p = &sAh[row*AVPITCH + c];
            __half2 v = *(__half2*)p;
            *(__half2*)p = __hmul2(v, v);
        }
        __syncthreads();
    }

    float acc[2][2][4];
#pragma unroll
    for (int a=0;a<2;a++)
#pragma unroll
        for (int b=0;b<2;b++)
#pragma unroll
            for (int c=0;c<4;c++) acc[a][b][c]=0.f;

    for (int s=0;s<13;s++){
        int kc = s*8 + tig;
        uint32_t b0[2], b1[2];
#pragma unroll
        for (int nt=0;nt<2;nt++){
            int rb = wn*16 + nt*8 + g;
            b0[nt]=sB[rb*AVPITCH+kc]; b1[nt]=sB[rb*AVPITCH+kc+4];
        }
#pragma unroll
        for (int mt=0;mt<2;mt++){
            int r = wm*32 + mt*16 + g;
            uint32_t a0=sAh[r*AVPITCH+kc],     a1=sAh[(r+8)*AVPITCH+kc];
            uint32_t a2=sAh[r*AVPITCH+kc+4],   a3=sAh[(r+8)*AVPITCH+kc+4];
#pragma unroll
            for (int nt=0;nt<2;nt++){
                mma16816(acc[mt][nt], a0,a1,a2,a3, b0[nt],b1[nt]);
            }
        }
    }

    const int b = bh / NHEAD;
    const int hh = bh % NHEAD;
#pragma unroll
    for (int mt=0;mt<2;mt++){
#pragma unroll
        for (int hf=0;hf<2;hf++){
            int n = n0 + wm*32 + mt*16 + g + hf*8;
            if (n >= NTOK) continue;
            size_t row = (size_t)(path*MPAD + b*NTOK + n)*EMB + hh*64;
#pragma unroll
            for (int nt=0;nt<2;nt++){
                int d0 = wn*16 + nt*8 + tig*2;
                __half2 hv;
                hv.x = __float2half_rn(acc[mt][nt][hf*2]);
                hv.y = __float2half_rn(acc[mt][nt][hf*2+1]);
                *(__half2*)(ctx + row + d0) = hv;
            }
        }
    }
}

/* ------------------------------ tail ---------------------------------- */
__global__ void __launch_bounds__(256) pool_kernel(const float* __restrict__ xx, float* __restrict__ pool)
{
    int b = blockIdx.x;
    int tid=threadIdx.x;
#pragma unroll
    for (int r=0;r<3;r++){
        int e = tid + r*256;
        float s=0.f;
        for (int n=1;n<NTOK;n++) s += xx[((size_t)(b*NTOK+n))*EMB+e];
        pool[b*EMB+e]=s*(1.f/196.f);
    }
}

__global__ void head_kernel(const float* __restrict__ t, const float* __restrict__ w,
                            const float* __restrict__ hb, float* __restrict__ out)
{
    int idx = blockIdx.x*blockDim.x + threadIdx.x;
    if (idx >= BATCH*NCLS) return;
    int b = idx/NCLS, c = idx%NCLS;
    const float* tr = t + b*EMB;
    const float* wr = w + (size_t)c*EMB;
    float s = hb[c];
    for (int e=0;e<EMB;e+=4){
        float4 tv=*(const float4*)(tr+e);
        float4 wv=*(const float4*)(wr+e);
        s += tv.x*wv.x+tv.y*wv.y+tv.z*wv.z+tv.w*wv.w;
    }
    out[idx]=s;
}

/* ------------------------------ host ---------------------------------- */
extern "C" void kernel_launch(void* const* d_in, const int* in_sizes, int n_in,
                              void* d_out, int out_size)
{
    const float* x        = (const float*)d_in[0];
    const float* relb     = (const float*)d_in[1];
    const float* patch_w  = (const float*)d_in[2];
    const float* patch_b  = (const float*)d_in[3];
    const float* cpatch_w = (const float*)d_in[4];
    const float* cpatch_b = (const float*)d_in[5];
    const float* cls      = (const float*)d_in[6];
    const float* ccls     = (const float*)d_in[7];
    const float* n1g      = (const float*)d_in[8];
    const float* n1b      = (const float*)d_in[9];
    const float* qkvw     = (const float*)d_in[10];
    const float* qb       = (const float*)d_in[11];
    const float* vb       = (const float*)d_in[12];
    const float* cqb      = (const float*)d_in[13];
    const float* cvb      = (const float*)d_in[14];
    const float* projw    = (const float*)d_in[15];
    const float* projb    = (const float*)d_in[16];
    const float* cprojw   = (const float*)d_in[17];
    const float* cprojb   = (const float*)d_in[18];
    const float* gamma1   = (const float*)d_in[19];
    const float* gamma2   = (const float*)d_in[20];
    const float* n2g      = (const float*)d_in[21];
    const float* n2b      = (const float*)d_in[22];
    const float* fc1w     = (const float*)d_in[23];
    const float* fc1b     = (const float*)d_in[24];
    const float* fc2w     = (const float*)d_in[25];
    const float* fc2b     = (const float*)d_in[26];
    const float* fng      = (const float*)d_in[27];
    const float* fnb      = (const float*)d_in[28];
    const float* headw    = (const float*)d_in[29];
    const float* headb    = (const float*)d_in[30];
    float* out = (float*)d_out;

    static int attr_set = 0;
    if (!attr_set){
        cudaFuncSetAttribute(gemm_h, cudaFuncAttributeMaxDynamicSharedMemorySize, GEMM_SMEM);
        cudaFuncSetAttribute(score_mma, cudaFuncAttributeMaxDynamicSharedMemorySize, SC_SMEM);
        cudaFuncSetAttribute(av_mma, cudaFuncAttributeMaxDynamicSharedMemorySize, AV_SMEM);
        attr_set = 1;
    }

    __half *w,*pat,*tn,*ctx,*hbuf,*qkvh,*qph,*kp,*vt,*cvt,*sdot,*ahp,*relbh;
    float *p_x,*p_qstat,*p_kstat,*p_qkvb,*p_cqkvb,*p_pool,*p_pooln;
    cudaGetSymbolAddress((void**)&w, g_w);
    cudaGetSymbolAddress((void**)&pat, g_pat);
    cudaGetSymbolAddress((void**)&tn, g_tn);
    cudaGetSymbolAddress((void**)&ctx, g_ctx);
    cudaGetSymbolAddress((void**)&hbuf, g_h);
    cudaGetSymbolAddress((void**)&qkvh, g_qkv);
    cudaGetSymbolAddress((void**)&qph, g_qph);
    cudaGetSymbolAddress((void**)&kp,  g_kp);
    cudaGetSymbolAddress((void**)&vt,  g_vt);
    cudaGetSymbolAddress((void**)&cvt, g_cvt);
    cudaGetSymbolAddress((void**)&sdot,g_sdot);
    cudaGetSymbolAddress((void**)&ahp, g_ah);
    cudaGetSymbolAddress((void**)&relbh, g_relbh);
    cudaGetSymbolAddress((void**)&p_x,    g_x);
    cudaGetSymbolAddress((void**)&p_qstat,g_qstat);
    cudaGetSymbolAddress((void**)&p_kstat,g_kstat);
    cudaGetSymbolAddress((void**)&p_qkvb, g_qkvb);
    cudaGetSymbolAddress((void**)&p_cqkvb,g_cqkvb);
    cudaGetSymbolAddress((void**)&p_pool, g_pool);
    cudaGetSymbolAddress((void**)&p_pooln,g_pooln);

    auto wsp = [&](const float* src, size_t off, size_t cnt){
        size_t n4 = cnt/4;
        size_t n8 = n4/2;
        unsigned blocks = (unsigned)((n8 + 1023)/1024);
        wsplit_h<<<blocks,256>>>((const float4*)src, w+off, n4);
    };
    wsp(patch_w,  OFF_PW,    589824);
    wsp(cpatch_w, OFF_CPW,   589824);
    wsp(qkvw,     OFF_QKV,   21233664);
    wsp(projw,    OFF_PROJ,  7077888);
    wsp(cprojw,   OFF_CPROJ, 7077888);
    wsp(fc1w,     OFF_FC1,   28311552);
    wsp(fc2w,     OFF_FC2,   28311552);

    relb_h<<<(RELBN + 1023)/1024, 256>>>(relb, relbh, RELBN);
    build_qkvb<<<(NLAYER*E3+255)/256,256>>>(qb,vb,cqb,cvb,p_qkvb,p_cqkvb);
    im2col_split<<<(MROWS*EMB+255)/256,256>>>(x, pat);

    gemm_h<<<dim3(EMB/128,13,2),256,GEMM_SMEM>>>(
        pat, w+OFF_PW, w+OFF_CPW,
        patch_b, cpatch_b, nullptr, p_x, nullptr, EMB, EMB, EPI_BIAS, EPI_BIAS, 1);
    fill_cls<<<BATCH,256>>>(cls, ccls, p_x);

    for (int i=0;i<NLAYER;i++){
        size_t qkv_o  = OFF_QKV   + (size_t)i*E3*EMB;
        size_t proj_o = OFF_PROJ  + (size_t)i*EMB*EMB;
        size_t cprj_o = OFF_CPROJ + (size_t)i*EMB*EMB;
        size_t fc1_o  = OFF_FC1   + (size_t)i*(size_t)MLPD*EMB;
        size_t fc2_o  = OFF_FC2   + (size_t)i*(size_t)EMB*MLPD;

        ln_split<<<2*MROWS,256>>>(p_x, n1g+i*EMB, n1b+i*EMB, tn);
        gemm_h<<<dim3(E3/128,13,2),256,GEMM_SMEM>>>(
            tn, w+qkv_o, w+qkv_o,
            p_qkvb+i*E3, p_cqkvb+i*E3, nullptr, nullptr, qkvh,
            E3, EMB, EPI_QKVH, EPI_CQKVH, 0);

        attn_pre<<<BATCH*NHEAD*NTOK/4,256>>>(qkvh, qph,kp,vt,cvt,
                                             p_qstat,p_kstat);
        score_mma<<<dim3(4,4,BH),256,SC_SMEM>>>(qph,kp,sdot);
        attn_softmax<<<dim3(13,BH),256>>>(sdot,p_qstat,p_kstat,relbh,ahp);
        av_mma<<<dim3(4,BH,2),256,AV_SMEM>>>(ahp,vt,cvt,ctx);

        gemm_h<<<dim3(EMB/128,13,2),256,GEMM_SMEM>>>(
            ctx, w+proj_o, w+cprj_o,
            projb+i*EMB, cprojb+i*EMB, gamma1+i*EMB, p_x, nullptr,
            EMB, EMB, EPI_RES, EPI_RES, 0);

        ln_split<<<2*MROWS,256>>>(p_x, n2g+i*EMB, n2b+i*EMB, tn);
        gemm_h<<<dim3(MLPD/128,13,2),256,GEMM_SMEM>>>(
            tn, w+fc1_o, w+fc1_o,
            fc1b+i*MLPD, fc1b+i*MLPD, nullptr, nullptr, hbuf,
            MLPD, EMB, EPI_GELU, EPI_GELU, 0);
        gemm_h<<<dim3(EMB/128,13,2),256,GEMM_SMEM>>>(
            hbuf, w+fc2_o, w+fc2_o,
            fc2b+i*EMB, fc2b+i*EMB, gamma2+i*EMB, p_x, nullptr,
            EMB, MLPD, EPI_RES, EPI_RES, 0);
    }

    pool_kernel<<<BATCH,256>>>(p_x, p_pool);
    ln_f32<<<BATCH,256>>>(p_pool, fng, fnb, p_pooln);
    head_kernel<<<(BATCH*NCLS+255)/256,256>>>(p_pooln, headw, headb, out);
}